// round 6
// baseline (speedup 1.0000x reference)
#include <cuda_runtime.h>
#include <math.h>
#include <float.h>

// Problem dims
#define BB   2
#define TQ   2048
#define CM   1024
#define NH   16
#define DH   64
#define TKV  4096                       // 2048 cache + 2048 new
#define OUT_ELEMS (BB*TQ*CM)            // 4194304
#define KV_ELEMS  (BB*NH*TKV*DH)        // 8388608

// Scratch (allocation-free: device globals)
__device__ __align__(16) float g_q[BB*NH*TQ*DH];    // [b,h,t,d]
__device__ __align__(16) float g_kf[KV_ELEMS];      // [b,h,tk,d] == output k
__device__ __align__(16) float g_vf[KV_ELEMS];      // [b,h,tk,d] == output v
__device__ __align__(16) float g_attn[OUT_ELEMS];   // [b,t,c] pre-Wo

// ---------------------------------------------------------------------------
// Copy kv caches into rows [0, 2048) of the full K/V buffers
// ---------------------------------------------------------------------------
__global__ void copy_cache_kernel(const float4* __restrict__ kc,
                                  const float4* __restrict__ vc) {
    int idx = blockIdx.x * blockDim.x + threadIdx.x;
    const int total4 = BB * NH * 2048 * DH / 4;
    if (idx >= total4) return;
    int e  = idx << 2;
    int d  = e & (DH - 1);
    int t  = (e >> 6) & 2047;
    int bh = e >> 17;                 // 64*2048 = 2^17
    int dst4 = (((bh * TKV) + t) * DH + d) >> 2;
    ((float4*)g_kf)[dst4] = kc[idx];
    ((float4*)g_vf)[dst4] = vc[idx];
}

// ---------------------------------------------------------------------------
// 128x128x8 fp32 SGEMM, 256 threads, 8x8 register microtile.
// Y[m,n] = A[m,:] @ W[:,n] + bias[n]
// MODE 0: A = g_attn, write Cout[m*CM+n]   (output projection)
// MODE 1: write Q    -> g_q [b,h,t,d]
// MODE 2: write Knew -> g_kf rows 2048+t
// MODE 3: write Vnew -> g_vf rows 2048+t
// ---------------------------------------------------------------------------
template <int MODE>
__global__ void __launch_bounds__(256)
sgemm_kernel(const float* __restrict__ A,
             const float* __restrict__ W,
             const float* __restrict__ bias,
             float* __restrict__ Cout) {
    __shared__ float As[8][128];   // transposed A tile [k][m]
    __shared__ float Bs[8][128];   // natural W tile   [k][n]

    const float* Ap = (MODE == 0) ? (const float*)g_attn : A;

    int tid = threadIdx.x;
    int tx = tid & 15, ty = tid >> 4;
    int m0 = blockIdx.y * 128, n0 = blockIdx.x * 128;

    int arow = tid >> 1, acol = (tid & 1) << 2;   // A: 128 rows x 8 k-cols
    int brow = tid >> 5, bcol = (tid & 31) << 2;  // W: 8 k-rows x 128 n-cols
    const float* aptr = Ap + (size_t)(m0 + arow) * CM + acol;
    const float* bptr = W + (size_t)brow * CM + n0 + bcol;

    float acc[8][8];
#pragma unroll
    for (int i = 0; i < 8; i++)
#pragma unroll
        for (int j = 0; j < 8; j++) acc[i][j] = 0.f;

    for (int kt = 0; kt < CM; kt += 8) {
        float4 av = *(const float4*)(aptr + kt);
        float4 bv = *(const float4*)(bptr + (size_t)kt * CM);
        __syncthreads();
        As[acol + 0][arow] = av.x;
        As[acol + 1][arow] = av.y;
        As[acol + 2][arow] = av.z;
        As[acol + 3][arow] = av.w;
        *(float4*)&Bs[brow][bcol] = bv;
        __syncthreads();
#pragma unroll
        for (int k = 0; k < 8; k++) {
            float4 a0 = *(const float4*)&As[k][ty << 2];
            float4 a1 = *(const float4*)&As[k][64 + (ty << 2)];
            float4 b0 = *(const float4*)&Bs[k][tx << 2];
            float4 b1 = *(const float4*)&Bs[k][64 + (tx << 2)];
            float af[8] = {a0.x, a0.y, a0.z, a0.w, a1.x, a1.y, a1.z, a1.w};
            float bf[8] = {b0.x, b0.y, b0.z, b0.w, b1.x, b1.y, b1.z, b1.w};
#pragma unroll
            for (int i = 0; i < 8; i++)
#pragma unroll
                for (int j = 0; j < 8; j++)
                    acc[i][j] = fmaf(af[i], bf[j], acc[i][j]);
        }
    }

#pragma unroll
    for (int i = 0; i < 8; i++) {
        int m = m0 + ((i < 4) ? ((ty << 2) + i) : (64 + (ty << 2) + i - 4));
#pragma unroll
        for (int j = 0; j < 8; j++) {
            int n = n0 + ((j < 4) ? ((tx << 2) + j) : (64 + (tx << 2) + j - 4));
            float v = acc[i][j] + bias[n];
            if (MODE == 0) {
                Cout[(size_t)m * CM + n] = v;
            } else {
                int b = m >> 11, t = m & 2047;    // m = b*2048 + t
                int h = n >> 6, d = n & 63;       // n = h*64 + d
                if (MODE == 1)
                    g_q[((((size_t)b * NH) + h) * TQ + t) * DH + d] = v;
                else if (MODE == 2)
                    g_kf[((((size_t)b * NH) + h) * TKV + 2048 + t) * DH + d] = v;
                else
                    g_vf[((((size_t)b * NH) + h) * TKV + 2048 + t) * DH + d] = v;
            }
        }
    }
}

// ---------------------------------------------------------------------------
// fp32 flash attention. One CTA = 64 q-rows of one (b,h).
// Causal: query i (global) attends keys j <= i + 2048.
// q-tile qt: k-tiles 0..qt+31 are fully unmasked, kt==qt+32 is the triangular
// diagonal tile, later tiles are skipped entirely.
// Thread map: 16x16 grid, thread (ty,tx) owns S/P rows 4ty..+3, cols 4tx..+3,
// and O rows 4ty..+3, dims 4tx..+3.
// ---------------------------------------------------------------------------
__global__ void __launch_bounds__(256) flash_kernel() {
    extern __shared__ float sm[];
    float* Qt = sm;               // [64][64]  d-major  (Qt[d*64+r])
    float* Kt = sm + 4096;        // [64][68]  d-major  (Kt[d*68+c], padded)
    float* Vs = Kt + 64 * 68;     // [64][64]  natural  (Vs[c*64+n])
    float* Ps = Vs + 4096;        // [64][64]  natural  (Ps[r*64+c])

    int qt = blockIdx.x, h = blockIdx.y, b = blockIdx.z;
    int tid = threadIdx.x;
    int tx = tid & 15, ty = tid >> 4;
    int bh = b * NH + h;
    int q0 = qt * 64;

    const float* qbase = g_q + ((size_t)bh * TQ + q0) * DH;
    const float* kbase = g_kf + (size_t)bh * TKV * DH;
    const float* vbase = g_vf + (size_t)bh * TKV * DH;

    // Load Q tile, transposed, pre-scaled by Dh^-0.5 = 1/8
#pragma unroll 4
    for (int i = tid; i < 1024; i += 256) {
        int r = i >> 4, d4 = (i & 15) << 2;
        float4 v = *(const float4*)(qbase + (size_t)r * DH + d4);
        Qt[(d4 + 0) * 64 + r] = v.x * 0.125f;
        Qt[(d4 + 1) * 64 + r] = v.y * 0.125f;
        Qt[(d4 + 2) * 64 + r] = v.z * 0.125f;
        Qt[(d4 + 3) * 64 + r] = v.w * 0.125f;
    }

    float mrow[4], lrow[4], o[4][4];
#pragma unroll
    for (int i = 0; i < 4; i++) {
        mrow[i] = -FLT_MAX;
        lrow[i] = 0.f;
#pragma unroll
        for (int j = 0; j < 4; j++) o[i][j] = 0.f;
    }

    int nkt = qt + 33;
    for (int kt = 0; kt < nkt; kt++) {
        const float* kb = kbase + (size_t)kt * 64 * DH;
        const float* vb = vbase + (size_t)kt * 64 * DH;

        __syncthreads();  // prior PV reads of Vs/Ps done; Q stores visible
        // Load K (transposed) + V (natural)
#pragma unroll 4
        for (int i = tid; i < 1024; i += 256) {
            int c = i >> 4, d4 = (i & 15) << 2;
            float4 kv = *(const float4*)(kb + (size_t)c * DH + d4);
            Kt[(d4 + 0) * 68 + c] = kv.x;
            Kt[(d4 + 1) * 68 + c] = kv.y;
            Kt[(d4 + 2) * 68 + c] = kv.z;
            Kt[(d4 + 3) * 68 + c] = kv.w;
            float4 vv = *(const float4*)(vb + (size_t)c * DH + d4);
            *(float4*)&Vs[c * 64 + d4] = vv;
        }
        __syncthreads();

        // S = (Q*scale) @ K^T   (64x64x64)
        float s[4][4];
#pragma unroll
        for (int i = 0; i < 4; i++)
#pragma unroll
            for (int j = 0; j < 4; j++) s[i][j] = 0.f;
#pragma unroll 8
        for (int dd = 0; dd < 64; dd++) {
            float4 qv = *(const float4*)&Qt[dd * 64 + (ty << 2)];
            float4 kv = *(const float4*)&Kt[dd * 68 + (tx << 2)];
            float qa[4] = {qv.x, qv.y, qv.z, qv.w};
            float ka[4] = {kv.x, kv.y, kv.z, kv.w};
#pragma unroll
            for (int i = 0; i < 4; i++)
#pragma unroll
                for (int j = 0; j < 4; j++)
                    s[i][j] = fmaf(qa[i], ka[j], s[i][j]);
        }

        // Triangular mask only on the diagonal tile
        if (kt == qt + 32) {
#pragma unroll
            for (int i = 0; i < 4; i++)
#pragma unroll
                for (int j = 0; j < 4; j++)
                    if ((tx << 2) + j > (ty << 2) + i) s[i][j] = -FLT_MAX;
        }

        // Online softmax per row (reduction across 16 tx-lanes, same half-warp)
#pragma unroll
        for (int i = 0; i < 4; i++) {
            float mx = fmaxf(fmaxf(s[i][0], s[i][1]), fmaxf(s[i][2], s[i][3]));
#pragma unroll
            for (int off = 8; off > 0; off >>= 1)
                mx = fmaxf(mx, __shfl_xor_sync(0xffffffffu, mx, off));
            float mnew = fmaxf(mrow[i], mx);
            float alpha = __expf(mrow[i] - mnew);
            mrow[i] = mnew;
            float ls = 0.f;
#pragma unroll
            for (int j = 0; j < 4; j++) {
                float p = __expf(s[i][j] - mnew);
                s[i][j] = p;
                ls += p;
            }
#pragma unroll
            for (int off = 8; off > 0; off >>= 1)
                ls += __shfl_xor_sync(0xffffffffu, ls, off);
            lrow[i] = lrow[i] * alpha + ls;
#pragma unroll
            for (int j = 0; j < 4; j++) o[i][j] *= alpha;
            *(float4*)&Ps[((ty << 2) + i) * 64 + (tx << 2)] =
                make_float4(s[i][0], s[i][1], s[i][2], s[i][3]);
        }
        __syncthreads();

        // O += P @ V   (64x64x64)
#pragma unroll 8
        for (int cc = 0; cc < 64; cc++) {
            float pa[4];
#pragma unroll
            for (int i = 0; i < 4; i++) pa[i] = Ps[((ty << 2) + i) * 64 + cc];
            float4 vv = *(const float4*)&Vs[cc * 64 + (tx << 2)];
            float va[4] = {vv.x, vv.y, vv.z, vv.w};
#pragma unroll
            for (int i = 0; i < 4; i++)
#pragma unroll
                for (int j = 0; j < 4; j++)
                    o[i][j] = fmaf(pa[i], va[j], o[i][j]);
        }
    }

    // Epilogue: O / l  ->  g_attn[b, t, h*64 + d]
    float* obase = g_attn + ((size_t)b * TQ + q0) * CM + h * DH;
#pragma unroll
    for (int i = 0; i < 4; i++) {
        float inv = 1.f / lrow[i];
        int r = (ty << 2) + i;
        *(float4*)&obase[(size_t)r * CM + (tx << 2)] =
            make_float4(o[i][0] * inv, o[i][1] * inv, o[i][2] * inv, o[i][3] * inv);
    }
}

// ---------------------------------------------------------------------------
// Copy full K then V into the output tail (reference returns (out, (k, v)))
// ---------------------------------------------------------------------------
__global__ void copy_kv_kernel(float4* __restrict__ dst) {
    int idx = blockIdx.x * blockDim.x + threadIdx.x;
    const int n4 = KV_ELEMS / 4;
    if (idx < n4)
        dst[idx] = ((const float4*)g_kf)[idx];
    else if (idx < 2 * n4)
        dst[idx] = ((const float4*)g_vf)[idx - n4];
}

// ---------------------------------------------------------------------------
extern "C" void kernel_launch(void* const* d_in, const int* in_sizes, int n_in,
                              void* d_out, int out_size) {
    const float* x  = (const float*)d_in[0];
    const float* kc = (const float*)d_in[1];
    const float* vc = (const float*)d_in[2];
    const float* Wq = (const float*)d_in[3];
    const float* bq = (const float*)d_in[4];
    const float* Wk = (const float*)d_in[5];
    const float* bk = (const float*)d_in[6];
    const float* Wv = (const float*)d_in[7];
    const float* bv = (const float*)d_in[8];
    const float* Wo = (const float*)d_in[9];
    const float* bo = (const float*)d_in[10];
    float* out = (float*)d_out;
    (void)in_sizes; (void)n_in;

    const int FLASH_SMEM = (4096 + 64 * 68 + 4096 + 4096) * 4;  // 66560 B
    cudaFuncSetAttribute(flash_kernel,
                         cudaFuncAttributeMaxDynamicSharedMemorySize, FLASH_SMEM);

    {
        int total4 = BB * NH * 2048 * DH / 4;
        copy_cache_kernel<<<(total4 + 255) / 256, 256>>>(
            (const float4*)kc, (const float4*)vc);
    }

    dim3 ggrid(CM / 128, (BB * TQ) / 128);  // (8, 32)
    sgemm_kernel<1><<<ggrid, 256>>>(x, Wq, bq, nullptr);
    sgemm_kernel<2><<<ggrid, 256>>>(x, Wk, bk, nullptr);
    sgemm_kernel<3><<<ggrid, 256>>>(x, Wv, bv, nullptr);

    flash_kernel<<<dim3(TQ / 64, NH, BB), 256, FLASH_SMEM>>>();

    sgemm_kernel<0><<<ggrid, 256>>>(nullptr, Wo, bo, out);

    if (out_size >= OUT_ELEMS + 2 * KV_ELEMS) {
        int n4 = 2 * KV_ELEMS / 4;
        copy_kv_kernel<<<(n4 + 255) / 256, 256>>>((float4*)(out + OUT_ELEMS));
    }
}

// round 8
// speedup vs baseline: 2.9409x; 2.9409x over previous
#include <cuda_runtime.h>
#include <math.h>
#include <float.h>

// Problem dims
#define BB   2
#define TQ   2048
#define CM   1024
#define NH   16
#define DH   64
#define TKV  4096
#define OUT_ELEMS (BB*TQ*CM)            // 4194304
#define KV_ELEMS  (BB*NH*TKV*DH)        // 8388608

// Scratch (device globals; allocation-free)
__device__ __align__(16) float g_q[BB*NH*TQ*DH];    // [b,h,t,d]  tf32-rounded
__device__ __align__(16) float g_kf[KV_ELEMS];      // [b,h,tk,d] == output k
__device__ __align__(16) float g_vf[KV_ELEMS];      // [b,h,tk,d] == output v
__device__ __align__(16) float g_attn[OUT_ELEMS];   // [b,t,c]    tf32-rounded
__device__ __align__(16) float g_xr[OUT_ELEMS];     // x rounded to tf32
__device__ __align__(16) float g_wr[4*CM*CM];       // Wq,Wk,Wv,Wo rounded

// ---------------------------------------------------------------------------
// PTX helpers
// ---------------------------------------------------------------------------
__device__ __forceinline__ unsigned su32(const void* p) {
    return (unsigned)__cvta_generic_to_shared(p);
}
__device__ __forceinline__ void cpa16(void* d, const void* s) {
    asm volatile("cp.async.cg.shared.global [%0], [%1], 16;"
                 :: "r"(su32(d)), "l"(s));
}
#define CPC  asm volatile("cp.async.commit_group;")
#define CPW1 asm volatile("cp.async.wait_group 1;")
#define CPW0 asm volatile("cp.async.wait_group 0;")

__device__ __forceinline__ void ldsm4(unsigned* r, unsigned a) {
    asm volatile("ldmatrix.sync.aligned.m8n8.x4.shared.b16 {%0,%1,%2,%3}, [%4];"
                 : "=r"(r[0]), "=r"(r[1]), "=r"(r[2]), "=r"(r[3]) : "r"(a));
}
__device__ __forceinline__ void mma8(float* c, const unsigned* a,
                                     unsigned b0, unsigned b1) {
    asm volatile(
        "mma.sync.aligned.m16n8k8.row.col.f32.tf32.tf32.f32 "
        "{%0,%1,%2,%3}, {%4,%5,%6,%7}, {%8,%9}, {%0,%1,%2,%3};\n"
        : "+f"(c[0]), "+f"(c[1]), "+f"(c[2]), "+f"(c[3])
        : "r"(a[0]), "r"(a[1]), "r"(a[2]), "r"(a[3]), "r"(b0), "r"(b1));
}
__device__ __forceinline__ float tfr(float x) {   // round-to-nearest tf32
    unsigned u;
    asm("cvt.rna.tf32.f32 %0, %1;" : "=r"(u) : "f"(x));
    return __uint_as_float(u);
}
__device__ __forceinline__ float ex2(float x) {
    float y; asm("ex2.approx.f32 %0, %1;" : "=f"(y) : "f"(x)); return y;
}

// ---------------------------------------------------------------------------
// Pre-pass: round x and the 4 weight matrices to tf32 (rna)
// ---------------------------------------------------------------------------
__global__ void round_inputs_kernel(const float4* __restrict__ x,
                                    const float4* __restrict__ wq,
                                    const float4* __restrict__ wk,
                                    const float4* __restrict__ wv,
                                    const float4* __restrict__ wo) {
    int i = blockIdx.x * blockDim.x + threadIdx.x;
    const int NX = OUT_ELEMS / 4;          // 1048576
    const int NW = (CM * CM) / 4;          // 262144
    float4 v; float4* dst;
    if (i < NX) {
        v = x[i]; dst = (float4*)g_xr + i;
    } else {
        int j = i - NX;
        if (j >= 4 * NW) return;
        int ws = j / NW, off = j - ws * NW;
        const float4* src = (ws == 0) ? wq : (ws == 1) ? wk : (ws == 2) ? wv : wo;
        v = src[off];
        dst = (float4*)g_wr + (size_t)ws * NW + off;
    }
    v.x = tfr(v.x); v.y = tfr(v.y); v.z = tfr(v.z); v.w = tfr(v.w);
    *dst = v;
}

// ---------------------------------------------------------------------------
// Copy kv caches (exact fp32) into rows [0,2048) of the full K/V buffers
// ---------------------------------------------------------------------------
__global__ void copy_cache_kernel(const float4* __restrict__ kc,
                                  const float4* __restrict__ vc) {
    int idx = blockIdx.x * blockDim.x + threadIdx.x;
    const int total4 = BB * NH * 2048 * DH / 4;
    if (idx >= total4) return;
    int e  = idx << 2;
    int d  = e & (DH - 1);
    int t  = (e >> 6) & 2047;
    int bh = e >> 17;
    int dst4 = (((bh * TKV) + t) * DH + d) >> 2;
    ((float4*)g_kf)[dst4] = kc[idx];
    ((float4*)g_vf)[dst4] = vc[idx];
}

// ---------------------------------------------------------------------------
// tf32 tensor-core GEMM: 128x128 tile, kc=16, double-buffered cp.async.
// Y[m,n] = A[m,:] @ W[:,n] + bias[n]
// MODE 0: A=g_attn, W=Wo  -> Cout (exact fp32)
// MODE 1: A=g_xr,   W=Wq  -> g_q   [b,h,t,d]   (tf32-rounded)
// MODE 2: A=g_xr,   W=Wk  -> g_kf rows 2048+t  (tf32-rounded)
// MODE 3: A=g_xr,   W=Wv  -> g_vf rows 2048+t  (tf32-rounded)
// 8 warps: 4(m) x 2(n); warp tile 32m x 64n -> 2 m-tiles, 8 n-tiles.
// ---------------------------------------------------------------------------
template <int MODE>
__global__ void __launch_bounds__(256, 2)
mma_gemm_kernel(const float* __restrict__ bias, float* __restrict__ Cout) {
    __shared__ float As[2][128][20];   // [m][k] pad 20 (LDSM conflict-free)
    __shared__ float Bs[2][16][132];   // [k][n] pad 132 (LDS conflict-free)

    const float* Ap = (MODE == 0) ? (const float*)g_attn : (const float*)g_xr;
    const float* Wp = g_wr + (size_t)((MODE == 0) ? 3 : (MODE - 1)) * CM * CM;

    int tid = threadIdx.x;
    int w = tid >> 5, l = tid & 31, lg = l >> 2, lt = l & 3;
    int wm = w & 3, wn = w >> 2;
    int m0 = blockIdx.y * 128, n0 = blockIdx.x * 128;

    auto loadAB = [&](int buf, int kt) {
        int k0 = kt * 16;
#pragma unroll
        for (int i = 0; i < 2; i++) {
            int id = tid + i * 256;
            int row = id >> 2, c4 = (id & 3) << 2;
            cpa16(&As[buf][row][c4], Ap + (size_t)(m0 + row) * CM + k0 + c4);
            int kr = id >> 5, c = (id & 31) << 2;
            cpa16(&Bs[buf][kr][c], Wp + (size_t)(k0 + kr) * CM + n0 + c);
        }
    };

    float acc[2][8][4];
#pragma unroll
    for (int mt = 0; mt < 2; mt++)
#pragma unroll
        for (int nt = 0; nt < 8; nt++)
#pragma unroll
            for (int c = 0; c < 4; c++) acc[mt][nt][c] = 0.f;

    unsigned uAs = su32(&As[0][0][0]);

    loadAB(0, 0); CPC;
    loadAB(1, 1); CPC;
    CPW1; __syncthreads();

    for (int kt = 0; kt < CM / 16; kt++) {
        int buf = kt & 1;
#pragma unroll
        for (int ks = 0; ks < 2; ks++) {
            unsigned aF[2][4];
#pragma unroll
            for (int mt = 0; mt < 2; mt++) {
                int row = wm * 32 + mt * 16 + (((l >> 3) & 1) << 3) + (l & 7);
                int col = ks * 8 + ((l >> 4) << 2);
                ldsm4(aF[mt], uAs + (unsigned)(buf * 2560 + row * 20 + col) * 4u);
            }
#pragma unroll
            for (int nt = 0; nt < 8; nt++) {
                int k = ks * 8 + lt;
                int n = wn * 64 + nt * 8 + lg;
                unsigned b0 = __float_as_uint(Bs[buf][k][n]);
                unsigned b1 = __float_as_uint(Bs[buf][k + 4][n]);
                mma8(acc[0][nt], aF[0], b0, b1);
                mma8(acc[1][nt], aF[1], b0, b1);
            }
        }
        __syncthreads();
        if (kt + 2 < CM / 16) {
            loadAB(buf, kt + 2);
            CPC; CPW1;
        } else {
            CPW0;
        }
        __syncthreads();
    }

    // Epilogue
#pragma unroll
    for (int mt = 0; mt < 2; mt++)
#pragma unroll
        for (int nt = 0; nt < 8; nt++)
#pragma unroll
            for (int g = 0; g < 2; g++) {
                int m = m0 + wm * 32 + mt * 16 + lg + 8 * g;
                int n = n0 + wn * 64 + nt * 8 + 2 * lt;
                float v0 = acc[mt][nt][2 * g] + bias[n];
                float v1 = acc[mt][nt][2 * g + 1] + bias[n + 1];
                if (MODE == 0) {
                    *(float2*)&Cout[(size_t)m * CM + n] = make_float2(v0, v1);
                } else {
                    v0 = tfr(v0); v1 = tfr(v1);
                    int b = m >> 11, t = m & 2047;
                    int h = n >> 6, d = n & 63;
                    float* dst;
                    if (MODE == 1)
                        dst = &g_q[((((size_t)b * NH) + h) * TQ + t) * DH + d];
                    else if (MODE == 2)
                        dst = &g_kf[((((size_t)b * NH) + h) * TKV + 2048 + t) * DH + d];
                    else
                        dst = &g_vf[((((size_t)b * NH) + h) * TKV + 2048 + t) * DH + d];
                    *(float2*)dst = make_float2(v0, v1);
                }
            }
}

// ---------------------------------------------------------------------------
// tf32 tensor-core flash attention.
// CTA: Bq=128 q-rows of one (b,h); Bk=64; 8 warps, warp w = q rows [16w,16w+16).
// Causal: query i attends keys j <= i + 2048.
// K/V double-buffered via cp.async. Scale 1/8 folded into exp2 constant.
// ---------------------------------------------------------------------------
#define FL_C2 0.1803368801111f   /* 0.125 * log2(e) */

__global__ void __launch_bounds__(256, 1) flash_mma_kernel() {
    extern __shared__ float fsm[];
    float* Qs = fsm;                    // [128][68]
    float* Ks = Qs + 128 * 68;          // [2][64][68]
    float* Vs = Ks + 2 * 64 * 68;       // [2][64][68]
    float* Ps = Vs + 2 * 64 * 68;       // [128][68]

    int qt = 15 - blockIdx.x;           // heavy tiles first
    int h = blockIdx.y, b = blockIdx.z;
    int bh = b * NH + h;
    int q0 = qt * 128;
    int nkt = 2 * qt + 34;

    int tid = threadIdx.x;
    int w = tid >> 5, l = tid & 31, lg = l >> 2, lt = l & 3;
    int r0w = w * 16;

    const float* qb = g_q + ((size_t)bh * TQ + q0) * DH;
    const float* kb0 = g_kf + (size_t)bh * TKV * DH;
    const float* vb0 = g_vf + (size_t)bh * TKV * DH;

    unsigned uQs = su32(Qs), uKs = su32(Ks), uPs = su32(Ps);

    auto loadKV = [&](int buf, int kt) {
        const float* kb = kb0 + (size_t)kt * 64 * DH;
        const float* vb = vb0 + (size_t)kt * 64 * DH;
        float* Kd = Ks + buf * 64 * 68;
        float* Vd = Vs + buf * 64 * 68;
#pragma unroll
        for (int i = 0; i < 4; i++) {
            int id = tid + i * 256;
            int row = id >> 4, c4 = (id & 15) << 2;
            cpa16(Kd + row * 68 + c4, kb + row * DH + c4);
            cpa16(Vd + row * 68 + c4, vb + row * DH + c4);
        }
    };

    // Prologue: Q + KV(0) in group 0, KV(1) in group 1
#pragma unroll
    for (int i = 0; i < 8; i++) {
        int id = tid + i * 256;
        int row = id >> 4, c4 = (id & 15) << 2;
        cpa16(Qs + row * 68 + c4, qb + row * DH + c4);
    }
    loadKV(0, 0); CPC;
    loadKV(1, 1); CPC;
    CPW1; __syncthreads();

    float oacc[8][4];
    float mrow[2] = {-1e30f, -1e30f};
    float lrow[2] = {0.f, 0.f};
#pragma unroll
    for (int nt = 0; nt < 8; nt++)
#pragma unroll
        for (int c = 0; c < 4; c++) oacc[nt][c] = 0.f;

    for (int kt = 0; kt < nkt; kt++) {
        int buf = kt & 1;
        unsigned kbase = uKs + (unsigned)(buf * 64 * 68) * 4u;
        const float* Vb = Vs + buf * 64 * 68;

        // ---- S = Q @ K^T ----
        float sacc[8][4];
#pragma unroll
        for (int nt = 0; nt < 8; nt++)
#pragma unroll
            for (int c = 0; c < 4; c++) sacc[nt][c] = 0.f;

        unsigned aF[4], bF[4];
#pragma unroll
        for (int d8 = 0; d8 < 8; d8++) {
            {
                int row = r0w + (((l >> 3) & 1) << 3) + (l & 7);
                int col = d8 * 8 + ((l >> 4) << 2);
                ldsm4(aF, uQs + (unsigned)(row * 68 + col) * 4u);
            }
#pragma unroll
            for (int ntp = 0; ntp < 4; ntp++) {
                int row = ntp * 16 + ((l >> 4) << 3) + (l & 7);
                int col = d8 * 8 + (((l >> 3) & 1) << 2);
                ldsm4(bF, kbase + (unsigned)(row * 68 + col) * 4u);
                mma8(sacc[2 * ntp], aF, bF[0], bF[1]);
                mma8(sacc[2 * ntp + 1], aF, bF[2], bF[3]);
            }
        }

        // ---- causal mask (only near the frontier) ----
        int thresh = q0 + 2048 - kt * 64;
        if (thresh < 64) {
            int rbase = r0w + lg;
#pragma unroll
            for (int nt = 0; nt < 8; nt++) {
                int jj0 = nt * 8 + 2 * lt;
#pragma unroll
                for (int cr = 0; cr < 4; cr++) {
                    int r = rbase + ((cr >> 1) << 3);
                    int jj = jj0 + (cr & 1);
                    if (jj > r + thresh) sacc[nt][cr] = -1e30f;
                }
            }
        }

        // ---- online softmax (warp-local, quad reduce) ----
#pragma unroll
        for (int g = 0; g < 2; g++) {
            float mx = -1e30f;
#pragma unroll
            for (int nt = 0; nt < 8; nt++)
                mx = fmaxf(mx, fmaxf(sacc[nt][2 * g], sacc[nt][2 * g + 1]));
            mx = fmaxf(mx, __shfl_xor_sync(0xffffffffu, mx, 1));
            mx = fmaxf(mx, __shfl_xor_sync(0xffffffffu, mx, 2));
            float mnew = fmaxf(mrow[g], mx);
            float alpha = ex2((mrow[g] - mnew) * FL_C2);
            mrow[g] = mnew;
            float sum = 0.f;
#pragma unroll
            for (int nt = 0; nt < 8; nt++) {
#pragma unroll
                for (int c = 0; c < 2; c++) {
                    float p = ex2((sacc[nt][2 * g + c] - mnew) * FL_C2);
                    sacc[nt][2 * g + c] = p;
                    sum += p;
                }
            }
            sum += __shfl_xor_sync(0xffffffffu, sum, 1);
            sum += __shfl_xor_sync(0xffffffffu, sum, 2);
            lrow[g] = lrow[g] * alpha + sum;
#pragma unroll
            for (int nt = 0; nt < 8; nt++) {
                oacc[nt][2 * g] *= alpha;
                oacc[nt][2 * g + 1] *= alpha;
            }
        }

        // ---- store P (tf32-rounded), warp-private rows ----
#pragma unroll
        for (int g = 0; g < 2; g++) {
            int row = r0w + lg + 8 * g;
#pragma unroll
            for (int nt = 0; nt < 8; nt++) {
                *(float2*)(Ps + row * 68 + nt * 8 + 2 * lt) =
                    make_float2(tfr(sacc[nt][2 * g]), tfr(sacc[nt][2 * g + 1]));
            }
        }
        __syncwarp();

        // ---- O += P @ V ----
#pragma unroll
        for (int k8 = 0; k8 < 8; k8++) {
            {
                int row = r0w + (((l >> 3) & 1) << 3) + (l & 7);
                int col = k8 * 8 + ((l >> 4) << 2);
                ldsm4(aF, uPs + (unsigned)(row * 68 + col) * 4u);
            }
#pragma unroll
            for (int nt = 0; nt < 8; nt++) {
                unsigned b0 = __float_as_uint(Vb[(k8 * 8 + lt) * 68 + nt * 8 + lg]);
                unsigned b1 = __float_as_uint(Vb[(k8 * 8 + 4 + lt) * 68 + nt * 8 + lg]);
                mma8(oacc[nt], aF, b0, b1);
            }
        }

        __syncthreads();
        if (kt + 2 < nkt) {
            loadKV(buf, kt + 2);
            CPC; CPW1;
        } else {
            CPW0;
        }
        __syncthreads();
    }

    // ---- epilogue: O/l -> g_attn[b, t, h*64+d] (tf32-rounded) ----
#pragma unroll
    for (int g = 0; g < 2; g++) {
        float inv = 1.f / lrow[g];
        int rg = q0 + r0w + lg + 8 * g;
        float* ob = g_attn + ((size_t)b * TQ + rg) * CM + h * DH;
#pragma unroll
        for (int nt = 0; nt < 8; nt++) {
            *(float2*)(ob + nt * 8 + 2 * lt) =
                make_float2(tfr(oacc[nt][2 * g] * inv),
                            tfr(oacc[nt][2 * g + 1] * inv));
        }
    }
}

// ---------------------------------------------------------------------------
// Copy full K then V into the output tail
// ---------------------------------------------------------------------------
__global__ void copy_kv_kernel(float4* __restrict__ dst) {
    int idx = blockIdx.x * blockDim.x + threadIdx.x;
    const int n4 = KV_ELEMS / 4;
    if (idx < n4)
        dst[idx] = ((const float4*)g_kf)[idx];
    else if (idx < 2 * n4)
        dst[idx] = ((const float4*)g_vf)[idx - n4];
}

// ---------------------------------------------------------------------------
extern "C" void kernel_launch(void* const* d_in, const int* in_sizes, int n_in,
                              void* d_out, int out_size) {
    const float* x  = (const float*)d_in[0];
    const float* kc = (const float*)d_in[1];
    const float* vc = (const float*)d_in[2];
    const float* Wq = (const float*)d_in[3];
    const float* bq = (const float*)d_in[4];
    const float* Wk = (const float*)d_in[5];
    const float* bk = (const float*)d_in[6];
    const float* Wv = (const float*)d_in[7];
    const float* bv = (const float*)d_in[8];
    const float* Wo = (const float*)d_in[9];
    const float* bo = (const float*)d_in[10];
    float* out = (float*)d_out;
    (void)in_sizes; (void)n_in;

    const int FLASH_SMEM = (128 * 68 + 2 * 64 * 68 + 2 * 64 * 68 + 128 * 68) * 4;
    cudaFuncSetAttribute(flash_mma_kernel,
                         cudaFuncAttributeMaxDynamicSharedMemorySize, FLASH_SMEM);

    {
        int total4 = BB * NH * 2048 * DH / 4;
        copy_cache_kernel<<<(total4 + 255) / 256, 256>>>(
            (const float4*)kc, (const float4*)vc);
    }
    {
        int n4 = (OUT_ELEMS + 4 * CM * CM) / 4;
        round_inputs_kernel<<<(n4 + 255) / 256, 256>>>(
            (const float4*)x, (const float4*)Wq, (const float4*)Wk,
            (const float4*)Wv, (const float4*)Wo);
    }

    dim3 ggrid(CM / 128, (BB * TQ) / 128);  // (8, 32)
    mma_gemm_kernel<1><<<ggrid, 256>>>(bq, nullptr);
    mma_gemm_kernel<2><<<ggrid, 256>>>(bk, nullptr);
    mma_gemm_kernel<3><<<ggrid, 256>>>(bv, nullptr);

    flash_mma_kernel<<<dim3(TQ / 128, NH, BB), 256, FLASH_SMEM>>>();

    mma_gemm_kernel<0><<<ggrid, 256>>>(bo, out);

    if (out_size >= OUT_ELEMS + 2 * KV_ELEMS) {
        int n4 = 2 * KV_ELEMS / 4;
        copy_kv_kernel<<<(n4 + 255) / 256, 256>>>((float4*)(out + OUT_ELEMS));
    }
}

// round 10
// speedup vs baseline: 3.0485x; 1.0366x over previous
#include <cuda_runtime.h>
#include <math.h>
#include <float.h>

// Problem dims
#define BB   2
#define TQ   2048
#define CM   1024
#define NH   16
#define DH   64
#define TKV  4096
#define OUT_ELEMS (BB*TQ*CM)            // 4194304
#define KV_ELEMS  (BB*NH*TKV*DH)        // 8388608

// Scratch (device globals; allocation-free)
__device__ __align__(16) float g_q[BB*NH*TQ*DH];    // [b,h,t,d]  tf32-rounded
__device__ __align__(16) float g_kf[KV_ELEMS];      // [b,h,tk,d]
__device__ __align__(16) float g_vf[KV_ELEMS];      // [b,h,tk,d]
__device__ __align__(16) float g_attn[OUT_ELEMS];   // [b,t,c]    tf32-rounded
__device__ __align__(16) float g_xr[OUT_ELEMS];     // x rounded to tf32
__device__ __align__(16) float g_wr[4*CM*CM];       // Wq,Wk,Wv,Wo rounded

// ---------------------------------------------------------------------------
// PTX helpers
// ---------------------------------------------------------------------------
__device__ __forceinline__ unsigned su32(const void* p) {
    return (unsigned)__cvta_generic_to_shared(p);
}
__device__ __forceinline__ void cpa16(void* d, const void* s) {
    asm volatile("cp.async.cg.shared.global [%0], [%1], 16;"
                 :: "r"(su32(d)), "l"(s));
}
#define CPC  asm volatile("cp.async.commit_group;")
#define CPW2 asm volatile("cp.async.wait_group 2;")

__device__ __forceinline__ void ldsm4(unsigned* r, unsigned a) {
    asm volatile("ldmatrix.sync.aligned.m8n8.x4.shared.b16 {%0,%1,%2,%3}, [%4];"
                 : "=r"(r[0]), "=r"(r[1]), "=r"(r[2]), "=r"(r[3]) : "r"(a));
}
__device__ __forceinline__ void mma8(float* c, const unsigned* a,
                                     unsigned b0, unsigned b1) {
    asm volatile(
        "mma.sync.aligned.m16n8k8.row.col.f32.tf32.tf32.f32 "
        "{%0,%1,%2,%3}, {%4,%5,%6,%7}, {%8,%9}, {%0,%1,%2,%3};\n"
        : "+f"(c[0]), "+f"(c[1]), "+f"(c[2]), "+f"(c[3])
        : "r"(a[0]), "r"(a[1]), "r"(a[2]), "r"(a[3]), "r"(b0), "r"(b1));
}
__device__ __forceinline__ float tfr(float x) {   // round-to-nearest tf32
    unsigned u;
    asm("cvt.rna.tf32.f32 %0, %1;" : "=r"(u) : "f"(x));
    return __uint_as_float(u);
}
__device__ __forceinline__ float ex2(float x) {
    float y; asm("ex2.approx.f32 %0, %1;" : "=f"(y) : "f"(x)); return y;
}

// ---------------------------------------------------------------------------
// Pre-pass: round x and the 4 weight matrices to tf32 (rna)
// ---------------------------------------------------------------------------
__global__ void round_inputs_kernel(const float4* __restrict__ x,
                                    const float4* __restrict__ wq,
                                    const float4* __restrict__ wk,
                                    const float4* __restrict__ wv,
                                    const float4* __restrict__ wo) {
    int i = blockIdx.x * blockDim.x + threadIdx.x;
    const int NX = OUT_ELEMS / 4;
    const int NW = (CM * CM) / 4;
    float4 v; float4* dst;
    if (i < NX) {
        v = x[i]; dst = (float4*)g_xr + i;
    } else {
        int j = i - NX;
        if (j >= 4 * NW) return;
        int ws = j / NW, off = j - ws * NW;
        const float4* src = (ws == 0) ? wq : (ws == 1) ? wk : (ws == 2) ? wv : wo;
        v = src[off];
        dst = (float4*)g_wr + (size_t)ws * NW + off;
    }
    v.x = tfr(v.x); v.y = tfr(v.y); v.z = tfr(v.z); v.w = tfr(v.w);
    *dst = v;
}

// ---------------------------------------------------------------------------
// Copy kv caches (exact fp32) into rows [0,2048) of K/V buffers + output tail
// ---------------------------------------------------------------------------
template <int TAIL>
__global__ void copy_cache_kernel(const float4* __restrict__ kc,
                                  const float4* __restrict__ vc,
                                  float4* __restrict__ out_k,
                                  float4* __restrict__ out_v) {
    int idx = blockIdx.x * blockDim.x + threadIdx.x;
    const int total4 = BB * NH * 2048 * DH / 4;
    if (idx >= total4) return;
    int e  = idx << 2;
    int d  = e & (DH - 1);
    int t  = (e >> 6) & 2047;
    int bh = e >> 17;
    int dst4 = (((bh * TKV) + t) * DH + d) >> 2;
    float4 kv = kc[idx], vv = vc[idx];
    ((float4*)g_kf)[dst4] = kv;
    ((float4*)g_vf)[dst4] = vv;
    if (TAIL) { out_k[dst4] = kv; out_v[dst4] = vv; }
}

// ---------------------------------------------------------------------------
// tf32 tensor-core GEMM: 128x128 tile, kc=16, 3-stage cp.async pipeline.
// MODE 0: A=g_attn, W=Wo  -> Cout[m*CM+n] (exact fp32 output projection)
// MODE 1: fused QKV. blockIdx.x in [0,24): sec = bx>>3 (0=Q,1=K,2=V),
//         n0 = (bx&7)*128. Epilogue scatters tf32-rounded into g_q/g_kf/g_vf;
//         TAIL=1 additionally writes UNROUNDED values into the output k/v tail
//         (Cout = out + OUT_ELEMS; v-tail at Cout + KV_ELEMS).
// 8 warps: 4(m) x 2(n); warp tile 32m x 64n.
// ---------------------------------------------------------------------------
#define GEMM_SMEM ((3*128*20 + 3*16*132) * 4)   // 56064 B

template <int MODE, int TAIL>
__global__ void __launch_bounds__(256, 2)
mma_gemm_kernel(const float* __restrict__ b0p, const float* __restrict__ b1p,
                const float* __restrict__ b2p, float* __restrict__ Cout) {
    extern __shared__ float gsm[];
    float* As = gsm;                 // [3][128][20]
    float* Bs = gsm + 3 * 128 * 20;  // [3][16][132]

    int sec, n0;
    const float* Ap; const float* Wp; const float* bias;
    if (MODE == 0) {
        Ap = g_attn; Wp = g_wr + (size_t)3 * CM * CM; bias = b0p;
        n0 = blockIdx.x * 128; sec = 0;
    } else {
        Ap = g_xr;
        sec = blockIdx.x >> 3;
        n0 = (blockIdx.x & 7) * 128;
        Wp = g_wr + (size_t)sec * CM * CM;
        bias = (sec == 0) ? b0p : (sec == 1) ? b1p : b2p;
    }

    int tid = threadIdx.x;
    int w = tid >> 5, l = tid & 31, lg = l >> 2, lt = l & 3;
    int wm = w & 3, wn = w >> 2;
    int m0 = blockIdx.y * 128;

    auto loadAB = [&](int buf, int kt) {
        int k0 = kt * 16;
        float* Ad = As + buf * 2560;
        float* Bd = Bs + buf * 2112;
#pragma unroll
        for (int i = 0; i < 2; i++) {
            int id = tid + i * 256;
            int row = id >> 2, c4 = (id & 3) << 2;
            cpa16(Ad + row * 20 + c4, Ap + (size_t)(m0 + row) * CM + k0 + c4);
            int kr = id >> 5, c = (id & 31) << 2;
            cpa16(Bd + kr * 132 + c, Wp + (size_t)(k0 + kr) * CM + n0 + c);
        }
    };

    float acc[2][8][4];
#pragma unroll
    for (int mt = 0; mt < 2; mt++)
#pragma unroll
        for (int nt = 0; nt < 8; nt++)
#pragma unroll
            for (int c = 0; c < 4; c++) acc[mt][nt][c] = 0.f;

    unsigned uAs = su32(As);

    loadAB(0, 0); CPC;
    loadAB(1, 1); CPC;
    loadAB(2, 2); CPC;

    int buf = 0;
    for (int kt = 0; kt < CM / 16; kt++) {
        CPW2; __syncthreads();
        const float* Bb = Bs + buf * 2112;
#pragma unroll
        for (int ks = 0; ks < 2; ks++) {
            unsigned aF[2][4];
#pragma unroll
            for (int mt = 0; mt < 2; mt++) {
                int row = wm * 32 + mt * 16 + (((l >> 3) & 1) << 3) + (l & 7);
                int col = ks * 8 + ((l >> 4) << 2);
                ldsm4(aF[mt], uAs + (unsigned)(buf * 2560 + row * 20 + col) * 4u);
            }
#pragma unroll
            for (int nt = 0; nt < 8; nt++) {
                int k = ks * 8 + lt;
                int n = wn * 64 + nt * 8 + lg;
                unsigned b0 = __float_as_uint(Bb[k * 132 + n]);
                unsigned b1 = __float_as_uint(Bb[(k + 4) * 132 + n]);
                mma8(acc[0][nt], aF[0], b0, b1);
                mma8(acc[1][nt], aF[1], b0, b1);
            }
        }
        __syncthreads();
        if (kt + 3 < CM / 16) loadAB(buf, kt + 3);
        CPC;   // empty commits near the tail keep wait_group arithmetic exact
        buf = (buf == 2) ? 0 : buf + 1;
    }

    // Epilogue
#pragma unroll
    for (int mt = 0; mt < 2; mt++)
#pragma unroll
        for (int nt = 0; nt < 8; nt++)
#pragma unroll
            for (int g = 0; g < 2; g++) {
                int m = m0 + wm * 32 + mt * 16 + lg + 8 * g;
                int n = n0 + wn * 64 + nt * 8 + 2 * lt;
                float v0 = acc[mt][nt][2 * g] + bias[n];
                float v1 = acc[mt][nt][2 * g + 1] + bias[n + 1];
                if (MODE == 0) {
                    *(float2*)&Cout[(size_t)m * CM + n] = make_float2(v0, v1);
                } else {
                    int b = m >> 11, t = m & 2047;
                    int h = n >> 6, d = n & 63;
                    size_t off;
                    float* dst;
                    if (sec == 0) {
                        off = ((((size_t)b * NH) + h) * TQ + t) * DH + d;
                        dst = g_q + off;
                    } else {
                        off = ((((size_t)b * NH) + h) * TKV + 2048 + t) * DH + d;
                        dst = (sec == 1 ? g_kf : g_vf) + off;
                        if (TAIL) {   // unrounded values -> output k/v tail
                            float* tdst = (sec == 1 ? Cout : Cout + KV_ELEMS) + off;
                            *(float2*)tdst = make_float2(v0, v1);
                        }
                    }
                    *(float2*)dst = make_float2(tfr(v0), tfr(v1));
                }
            }
}

// ---------------------------------------------------------------------------
// tf32 tensor-core flash attention, 3-stage K/V pipeline.
// CTA: Bq=128 q-rows of one (b,h); Bk=64; 8 warps, warp w = q rows [16w,16w+16).
// ---------------------------------------------------------------------------
#define FL_C2 0.1803368801111f   /* 0.125 * log2(e) */
#define FLASH_SMEM ((128*68 + 3*64*68 + 3*64*68 + 128*68) * 4)  // 174080 B

__global__ void __launch_bounds__(256, 1) flash_mma_kernel() {
    extern __shared__ float fsm[];
    float* Qs = fsm;                    // [128][68]
    float* Ks = Qs + 128 * 68;          // [3][64][68]
    float* Vs = Ks + 3 * 64 * 68;       // [3][64][68]
    float* Ps = Vs + 3 * 64 * 68;       // [128][68]

    int qt = 15 - blockIdx.x;           // heavy tiles first
    int h = blockIdx.y, b = blockIdx.z;
    int bh = b * NH + h;
    int q0 = qt * 128;
    int nkt = 2 * qt + 34;

    int tid = threadIdx.x;
    int w = tid >> 5, l = tid & 31, lg = l >> 2, lt = l & 3;
    int r0w = w * 16;

    const float* qb = g_q + ((size_t)bh * TQ + q0) * DH;
    const float* kb0 = g_kf + (size_t)bh * TKV * DH;
    const float* vb0 = g_vf + (size_t)bh * TKV * DH;

    unsigned uQs = su32(Qs), uKs = su32(Ks), uPs = su32(Ps);

    auto loadKV = [&](int buf, int kt) {
        const float* kb = kb0 + (size_t)kt * 64 * DH;
        const float* vb = vb0 + (size_t)kt * 64 * DH;
        float* Kd = Ks + buf * 64 * 68;
        float* Vd = Vs + buf * 64 * 68;
#pragma unroll
        for (int i = 0; i < 4; i++) {
            int id = tid + i * 256;
            int row = id >> 4, c4 = (id & 15) << 2;
            cpa16(Kd + row * 68 + c4, kb + row * DH + c4);
            cpa16(Vd + row * 68 + c4, vb + row * DH + c4);
        }
    };

    // Prologue: group0={Q,KV0}, group1={KV1}, group2={KV2}
#pragma unroll
    for (int i = 0; i < 8; i++) {
        int id = tid + i * 256;
        int row = id >> 4, c4 = (id & 15) << 2;
        cpa16(Qs + row * 68 + c4, qb + row * DH + c4);
    }
    loadKV(0, 0); CPC;
    loadKV(1, 1); CPC;
    loadKV(2, 2); CPC;

    float oacc[8][4];
    float mrow[2] = {-1e30f, -1e30f};
    float lrow[2] = {0.f, 0.f};
#pragma unroll
    for (int nt = 0; nt < 8; nt++)
#pragma unroll
        for (int c = 0; c < 4; c++) oacc[nt][c] = 0.f;

    int buf = 0;
    for (int kt = 0; kt < nkt; kt++) {
        CPW2; __syncthreads();
        unsigned kbase = uKs + (unsigned)(buf * 64 * 68) * 4u;
        const float* Vb = Vs + buf * 64 * 68;

        // ---- S = Q @ K^T ----
        float sacc[8][4];
#pragma unroll
        for (int nt = 0; nt < 8; nt++)
#pragma unroll
            for (int c = 0; c < 4; c++) sacc[nt][c] = 0.f;

        unsigned aF[4], bF[4];
#pragma unroll
        for (int d8 = 0; d8 < 8; d8++) {
            {
                int row = r0w + (((l >> 3) & 1) << 3) + (l & 7);
                int col = d8 * 8 + ((l >> 4) << 2);
                ldsm4(aF, uQs + (unsigned)(row * 68 + col) * 4u);
            }
#pragma unroll
            for (int ntp = 0; ntp < 4; ntp++) {
                int row = ntp * 16 + ((l >> 4) << 3) + (l & 7);
                int col = d8 * 8 + (((l >> 3) & 1) << 2);
                ldsm4(bF, kbase + (unsigned)(row * 68 + col) * 4u);
                mma8(sacc[2 * ntp], aF, bF[0], bF[1]);
                mma8(sacc[2 * ntp + 1], aF, bF[2], bF[3]);
            }
        }

        // ---- causal mask (only near the frontier) ----
        int thresh = q0 + 2048 - kt * 64;
        if (thresh < 64) {
            int rbase = r0w + lg;
#pragma unroll
            for (int nt = 0; nt < 8; nt++) {
                int jj0 = nt * 8 + 2 * lt;
#pragma unroll
                for (int cr = 0; cr < 4; cr++) {
                    int r = rbase + ((cr >> 1) << 3);
                    int jj = jj0 + (cr & 1);
                    if (jj > r + thresh) sacc[nt][cr] = -1e30f;
                }
            }
        }

        // ---- online softmax (warp-local, quad reduce) ----
#pragma unroll
        for (int g = 0; g < 2; g++) {
            float mx = -1e30f;
#pragma unroll
            for (int nt = 0; nt < 8; nt++)
                mx = fmaxf(mx, fmaxf(sacc[nt][2 * g], sacc[nt][2 * g + 1]));
            mx = fmaxf(mx, __shfl_xor_sync(0xffffffffu, mx, 1));
            mx = fmaxf(mx, __shfl_xor_sync(0xffffffffu, mx, 2));
            float mnew = fmaxf(mrow[g], mx);
            float alpha = ex2((mrow[g] - mnew) * FL_C2);
            mrow[g] = mnew;
            float sum = 0.f;
#pragma unroll
            for (int nt = 0; nt < 8; nt++) {
#pragma unroll
                for (int c = 0; c < 2; c++) {
                    float p = ex2((sacc[nt][2 * g + c] - mnew) * FL_C2);
                    sacc[nt][2 * g + c] = p;
                    sum += p;
                }
            }
            sum += __shfl_xor_sync(0xffffffffu, sum, 1);
            sum += __shfl_xor_sync(0xffffffffu, sum, 2);
            lrow[g] = lrow[g] * alpha + sum;
#pragma unroll
            for (int nt = 0; nt < 8; nt++) {
                oacc[nt][2 * g] *= alpha;
                oacc[nt][2 * g + 1] *= alpha;
            }
        }

        // ---- store P (tf32-rounded), warp-private rows ----
#pragma unroll
        for (int g = 0; g < 2; g++) {
            int row = r0w + lg + 8 * g;
#pragma unroll
            for (int nt = 0; nt < 8; nt++) {
                *(float2*)(Ps + row * 68 + nt * 8 + 2 * lt) =
                    make_float2(tfr(sacc[nt][2 * g]), tfr(sacc[nt][2 * g + 1]));
            }
        }
        __syncwarp();

        // ---- O += P @ V ----
#pragma unroll
        for (int k8 = 0; k8 < 8; k8++) {
            {
                int row = r0w + (((l >> 3) & 1) << 3) + (l & 7);
                int col = k8 * 8 + ((l >> 4) << 2);
                ldsm4(aF, uPs + (unsigned)(row * 68 + col) * 4u);
            }
#pragma unroll
            for (int nt = 0; nt < 8; nt++) {
                unsigned b0 = __float_as_uint(Vb[(k8 * 8 + lt) * 68 + nt * 8 + lg]);
                unsigned b1 = __float_as_uint(Vb[(k8 * 8 + 4 + lt) * 68 + nt * 8 + lg]);
                mma8(oacc[nt], aF, b0, b1);
            }
        }

        __syncthreads();
        if (kt + 3 < nkt) loadKV(buf, kt + 3);
        CPC;   // empty commits near the tail keep wait_group arithmetic exact
        buf = (buf == 2) ? 0 : buf + 1;
    }

    // ---- epilogue: O/l -> g_attn[b, t, h*64+d] (tf32-rounded) ----
#pragma unroll
    for (int g = 0; g < 2; g++) {
        float inv = 1.f / lrow[g];
        int rg = q0 + r0w + lg + 8 * g;
        float* ob = g_attn + ((size_t)b * TQ + rg) * CM + h * DH;
#pragma unroll
        for (int nt = 0; nt < 8; nt++) {
            *(float2*)(ob + nt * 8 + 2 * lt) =
                make_float2(tfr(oacc[nt][2 * g] * inv),
                            tfr(oacc[nt][2 * g + 1] * inv));
        }
    }
}

// ---------------------------------------------------------------------------
extern "C" void kernel_launch(void* const* d_in, const int* in_sizes, int n_in,
                              void* d_out, int out_size) {
    const float* x  = (const float*)d_in[0];
    const float* kc = (const float*)d_in[1];
    const float* vc = (const float*)d_in[2];
    const float* Wq = (const float*)d_in[3];
    const float* bq = (const float*)d_in[4];
    const float* Wk = (const float*)d_in[5];
    const float* bk = (const float*)d_in[6];
    const float* Wv = (const float*)d_in[7];
    const float* bv = (const float*)d_in[8];
    const float* Wo = (const float*)d_in[9];
    const float* bo = (const float*)d_in[10];
    float* out = (float*)d_out;
    (void)in_sizes; (void)n_in;

    int tail = (out_size >= OUT_ELEMS + 2 * KV_ELEMS);

    cudaFuncSetAttribute(flash_mma_kernel,
                         cudaFuncAttributeMaxDynamicSharedMemorySize, FLASH_SMEM);
    cudaFuncSetAttribute(mma_gemm_kernel<1, 1>,
                         cudaFuncAttributeMaxDynamicSharedMemorySize, GEMM_SMEM);
    cudaFuncSetAttribute(mma_gemm_kernel<1, 0>,
                         cudaFuncAttributeMaxDynamicSharedMemorySize, GEMM_SMEM);
    cudaFuncSetAttribute(mma_gemm_kernel<0, 0>,
                         cudaFuncAttributeMaxDynamicSharedMemorySize, GEMM_SMEM);

    {
        int total4 = BB * NH * 2048 * DH / 4;
        int nb = (total4 + 255) / 256;
        if (tail)
            copy_cache_kernel<1><<<nb, 256>>>(
                (const float4*)kc, (const float4*)vc,
                (float4*)(out + OUT_ELEMS), (float4*)(out + OUT_ELEMS + KV_ELEMS));
        else
            copy_cache_kernel<0><<<nb, 256>>>(
                (const float4*)kc, (const float4*)vc, nullptr, nullptr);
    }
    {
        int n4 = (OUT_ELEMS + 4 * CM * CM) / 4;
        round_inputs_kernel<<<(n4 + 255) / 256, 256>>>(
            (const float4*)x, (const float4*)Wq, (const float4*)Wk,
            (const float4*)Wv, (const float4*)Wo);
    }

    // Fused QKV projection: one launch, 768 CTAs
    dim3 qkvgrid(24, (BB * TQ) / 128);
    if (tail)
        mma_gemm_kernel<1, 1><<<qkvgrid, 256, GEMM_SMEM>>>(
            bq, bk, bv, out + OUT_ELEMS);
    else
        mma_gemm_kernel<1, 0><<<qkvgrid, 256, GEMM_SMEM>>>(
            bq, bk, bv, nullptr);

    flash_mma_kernel<<<dim3(TQ / 128, NH, BB), 256, FLASH_SMEM>>>();

    mma_gemm_kernel<0, 0><<<dim3(CM / 128, (BB * TQ) / 128), 256, GEMM_SMEM>>>(
        bo, nullptr, nullptr, out);
}

// round 11
// speedup vs baseline: 3.4638x; 1.1362x over previous
#include <cuda_runtime.h>
#include <math.h>
#include <float.h>

// Problem dims
#define BB   2
#define TQ   2048
#define CM   1024
#define NH   16
#define DH   64
#define TKV  4096
#define OUT_ELEMS (BB*TQ*CM)            // 4194304
#define KV_ELEMS  (BB*NH*TKV*DH)        // 8388608

// Scratch (device globals; allocation-free)
__device__ __align__(16) float g_q[BB*NH*TQ*DH];    // [b,h,t,d]  tf32-rounded
__device__ __align__(16) float g_kf[KV_ELEMS];      // [b,h,tk,d]
__device__ __align__(16) float g_vf[KV_ELEMS];      // [b,h,d,tk]  TRANSPOSED
__device__ __align__(16) float g_attn[OUT_ELEMS];   // [b,t,c]    tf32-rounded
__device__ __align__(16) float g_xr[OUT_ELEMS];     // x rounded to tf32
__device__ __align__(16) float g_wr[4*CM*CM];       // Wq,Wk,Wv,Wo rounded

// ---------------------------------------------------------------------------
// PTX helpers
// ---------------------------------------------------------------------------
__device__ __forceinline__ unsigned su32(const void* p) {
    return (unsigned)__cvta_generic_to_shared(p);
}
__device__ __forceinline__ void cpa16(void* d, const void* s) {
    asm volatile("cp.async.cg.shared.global [%0], [%1], 16;"
                 :: "r"(su32(d)), "l"(s));
}
#define CPC  asm volatile("cp.async.commit_group;")
#define CPW2 asm volatile("cp.async.wait_group 2;")

__device__ __forceinline__ void ldsm4(unsigned* r, unsigned a) {
    asm volatile("ldmatrix.sync.aligned.m8n8.x4.shared.b16 {%0,%1,%2,%3}, [%4];"
                 : "=r"(r[0]), "=r"(r[1]), "=r"(r[2]), "=r"(r[3]) : "r"(a));
}
__device__ __forceinline__ void mma8(float* c, const unsigned* a,
                                     unsigned b0, unsigned b1) {
    asm volatile(
        "mma.sync.aligned.m16n8k8.row.col.f32.tf32.tf32.f32 "
        "{%0,%1,%2,%3}, {%4,%5,%6,%7}, {%8,%9}, {%0,%1,%2,%3};\n"
        : "+f"(c[0]), "+f"(c[1]), "+f"(c[2]), "+f"(c[3])
        : "r"(a[0]), "r"(a[1]), "r"(a[2]), "r"(a[3]), "r"(b0), "r"(b1));
}
__device__ __forceinline__ float tfr(float x) {   // round-to-nearest tf32
    unsigned u;
    asm("cvt.rna.tf32.f32 %0, %1;" : "=r"(u) : "f"(x));
    return __uint_as_float(u);
}
__device__ __forceinline__ float ex2(float x) {
    float y; asm("ex2.approx.f32 %0, %1;" : "=f"(y) : "f"(x)); return y;
}

// ---------------------------------------------------------------------------
// Pre-pass: round x and the 4 weight matrices to tf32 (rna)
// ---------------------------------------------------------------------------
__global__ void round_inputs_kernel(const float4* __restrict__ x,
                                    const float4* __restrict__ wq,
                                    const float4* __restrict__ wk,
                                    const float4* __restrict__ wv,
                                    const float4* __restrict__ wo) {
    int i = blockIdx.x * blockDim.x + threadIdx.x;
    const int NX = OUT_ELEMS / 4;
    const int NW = (CM * CM) / 4;
    float4 v; float4* dst;
    if (i < NX) {
        v = x[i]; dst = (float4*)g_xr + i;
    } else {
        int j = i - NX;
        if (j >= 4 * NW) return;
        int ws = j / NW, off = j - ws * NW;
        const float4* src = (ws == 0) ? wq : (ws == 1) ? wk : (ws == 2) ? wv : wo;
        v = src[off];
        dst = (float4*)g_wr + (size_t)ws * NW + off;
    }
    v.x = tfr(v.x); v.y = tfr(v.y); v.z = tfr(v.z); v.w = tfr(v.w);
    *dst = v;
}

// ---------------------------------------------------------------------------
// Copy k cache into rows [0,2048) of g_kf + exact k/v tails to output
// ---------------------------------------------------------------------------
template <int TAIL>
__global__ void copy_cache_kernel(const float4* __restrict__ kc,
                                  const float4* __restrict__ vc,
                                  float4* __restrict__ out_k,
                                  float4* __restrict__ out_v) {
    int idx = blockIdx.x * blockDim.x + threadIdx.x;
    const int total4 = BB * NH * 2048 * DH / 4;
    if (idx >= total4) return;
    int e  = idx << 2;
    int d  = e & (DH - 1);
    int t  = (e >> 6) & 2047;
    int bh = e >> 17;
    int dst4 = (((bh * TKV) + t) * DH + d) >> 2;
    float4 kv = kc[idx];
    ((float4*)g_kf)[dst4] = kv;
    if (TAIL) { out_k[dst4] = kv; out_v[dst4] = vc[idx]; }
}

// ---------------------------------------------------------------------------
// Transpose v cache [bh][t][d] -> g_vf [bh][d][t]  (t in [0,2048))
// 32x32 smem tiles, coalesced both directions.
// ---------------------------------------------------------------------------
__global__ void transpose_vcache_kernel(const float* __restrict__ vc) {
    __shared__ float tile[32][33];
    int bh = blockIdx.z;
    int c0 = blockIdx.x * 32, d0 = blockIdx.y * 32;
    int tx = threadIdx.x, ty = threadIdx.y;   // 32 x 8
    const float* src = vc + ((size_t)bh * 2048 + c0) * DH + d0;
#pragma unroll
    for (int j = 0; j < 32; j += 8)
        tile[ty + j][tx] = src[(size_t)(ty + j) * DH + tx];
    __syncthreads();
    float* dst = g_vf + ((size_t)bh * DH + d0) * TKV + c0;
#pragma unroll
    for (int j = 0; j < 32; j += 8)
        dst[(size_t)(ty + j) * TKV + tx] = tile[tx][ty + j];
}

// ---------------------------------------------------------------------------
// tf32 tensor-core GEMM: 128x128 tile, kc=16, 3-stage cp.async pipeline.
// MODE 0: A=g_attn, W=Wo  -> Cout[m*CM+n] (exact fp32 output projection)
// MODE 1: fused QKV. sec = bx>>3 (0=Q,1=K,2=V), n0=(bx&7)*128.
//         Q -> g_q [b,h,t,d]; K -> g_kf rows 2048+t; V -> g_vf TRANSPOSED
//         [bh][d][2048+t]. TAIL=1 also writes UNROUNDED k/v into output tail.
// ---------------------------------------------------------------------------
#define GEMM_SMEM ((3*128*20 + 3*16*132) * 4)   // 56064 B

template <int MODE, int TAIL>
__global__ void __launch_bounds__(256, 2)
mma_gemm_kernel(const float* __restrict__ b0p, const float* __restrict__ b1p,
                const float* __restrict__ b2p, float* __restrict__ Cout) {
    extern __shared__ float gsm[];
    float* As = gsm;                 // [3][128][20]
    float* Bs = gsm + 3 * 128 * 20;  // [3][16][132]

    int sec, n0;
    const float* Ap; const float* Wp; const float* bias;
    if (MODE == 0) {
        Ap = g_attn; Wp = g_wr + (size_t)3 * CM * CM; bias = b0p;
        n0 = blockIdx.x * 128; sec = 0;
    } else {
        Ap = g_xr;
        sec = blockIdx.x >> 3;
        n0 = (blockIdx.x & 7) * 128;
        Wp = g_wr + (size_t)sec * CM * CM;
        bias = (sec == 0) ? b0p : (sec == 1) ? b1p : b2p;
    }

    int tid = threadIdx.x;
    int w = tid >> 5, l = tid & 31, lg = l >> 2, lt = l & 3;
    int wm = w & 3, wn = w >> 2;
    int m0 = blockIdx.y * 128;

    auto loadAB = [&](int buf, int kt) {
        int k0 = kt * 16;
        float* Ad = As + buf * 2560;
        float* Bd = Bs + buf * 2112;
#pragma unroll
        for (int i = 0; i < 2; i++) {
            int id = tid + i * 256;
            int row = id >> 2, c4 = (id & 3) << 2;
            cpa16(Ad + row * 20 + c4, Ap + (size_t)(m0 + row) * CM + k0 + c4);
            int kr = id >> 5, c = (id & 31) << 2;
            cpa16(Bd + kr * 132 + c, Wp + (size_t)(k0 + kr) * CM + n0 + c);
        }
    };

    float acc[2][8][4];
#pragma unroll
    for (int mt = 0; mt < 2; mt++)
#pragma unroll
        for (int nt = 0; nt < 8; nt++)
#pragma unroll
            for (int c = 0; c < 4; c++) acc[mt][nt][c] = 0.f;

    unsigned uAs = su32(As);

    loadAB(0, 0); CPC;
    loadAB(1, 1); CPC;
    loadAB(2, 2); CPC;

    int buf = 0;
    for (int kt = 0; kt < CM / 16; kt++) {
        CPW2; __syncthreads();
        const float* Bb = Bs + buf * 2112;
#pragma unroll
        for (int ks = 0; ks < 2; ks++) {
            unsigned aF[2][4];
#pragma unroll
            for (int mt = 0; mt < 2; mt++) {
                int row = wm * 32 + mt * 16 + (((l >> 3) & 1) << 3) + (l & 7);
                int col = ks * 8 + ((l >> 4) << 2);
                ldsm4(aF[mt], uAs + (unsigned)(buf * 2560 + row * 20 + col) * 4u);
            }
#pragma unroll
            for (int nt = 0; nt < 8; nt++) {
                int k = ks * 8 + lt;
                int n = wn * 64 + nt * 8 + lg;
                unsigned b0 = __float_as_uint(Bb[k * 132 + n]);
                unsigned b1 = __float_as_uint(Bb[(k + 4) * 132 + n]);
                mma8(acc[0][nt], aF[0], b0, b1);
                mma8(acc[1][nt], aF[1], b0, b1);
            }
        }
        __syncthreads();
        if (kt + 3 < CM / 16) loadAB(buf, kt + 3);
        CPC;   // empty commits near the tail keep wait_group arithmetic exact
        buf = (buf == 2) ? 0 : buf + 1;
    }

    // Epilogue
#pragma unroll
    for (int mt = 0; mt < 2; mt++)
#pragma unroll
        for (int nt = 0; nt < 8; nt++)
#pragma unroll
            for (int g = 0; g < 2; g++) {
                int m = m0 + wm * 32 + mt * 16 + lg + 8 * g;
                int n = n0 + wn * 64 + nt * 8 + 2 * lt;
                float v0 = acc[mt][nt][2 * g] + bias[n];
                float v1 = acc[mt][nt][2 * g + 1] + bias[n + 1];
                if (MODE == 0) {
                    *(float2*)&Cout[(size_t)m * CM + n] = make_float2(v0, v1);
                } else {
                    int b = m >> 11, t = m & 2047;
                    int h = n >> 6, d = n & 63;
                    int bh = b * NH + h;
                    if (sec == 0) {
                        size_t off = ((size_t)bh * TQ + t) * DH + d;
                        *(float2*)(g_q + off) = make_float2(tfr(v0), tfr(v1));
                    } else if (sec == 1) {
                        size_t off = ((size_t)bh * TKV + 2048 + t) * DH + d;
                        *(float2*)(g_kf + off) = make_float2(tfr(v0), tfr(v1));
                        if (TAIL)
                            *(float2*)(Cout + off) = make_float2(v0, v1);
                    } else {
                        // transposed V scratch: [bh][d][2048+t]
                        size_t offT = ((size_t)bh * DH + d) * TKV + 2048 + t;
                        g_vf[offT]       = tfr(v0);
                        g_vf[offT + TKV] = tfr(v1);
                        if (TAIL) {
                            size_t off = ((size_t)bh * TKV + 2048 + t) * DH + d;
                            *(float2*)(Cout + KV_ELEMS + off) = make_float2(v0, v1);
                        }
                    }
                }
            }
}

// ---------------------------------------------------------------------------
// tf32 tensor-core flash attention, 3-stage K/V pipeline.
// CTA: Bq=128 q-rows of one (b,h); Bk=64; 8 warps, warp w = q rows [16w,16w+16).
// Q fragments hoisted (loop-invariant); V stored d-major -> conflict-free LDSM.
// ---------------------------------------------------------------------------
#define FL_C2 0.1803368801111f   /* 0.125 * log2(e) */
#define FLASH_SMEM ((128*68 + 3*64*68 + 3*64*68 + 128*68) * 4)  // 174080 B

__global__ void __launch_bounds__(256, 1) flash_mma_kernel() {
    extern __shared__ float fsm[];
    float* Qs = fsm;                    // [128][68]
    float* Ks = Qs + 128 * 68;          // [3][64][68]  (c-major: Ks[c][d])
    float* Vs = Ks + 3 * 64 * 68;       // [3][64][68]  (d-major: Vs[d][c])
    float* Ps = Vs + 3 * 64 * 68;       // [128][68]

    int qt = 15 - blockIdx.x;           // heavy tiles first
    int h = blockIdx.y, b = blockIdx.z;
    int bh = b * NH + h;
    int q0 = qt * 128;
    int nkt = 2 * qt + 34;

    int tid = threadIdx.x;
    int w = tid >> 5, l = tid & 31, lg = l >> 2, lt = l & 3;
    int r0w = w * 16;

    const float* qb = g_q + ((size_t)bh * TQ + q0) * DH;
    const float* kb0 = g_kf + (size_t)bh * TKV * DH;
    const float* vb0 = g_vf + (size_t)bh * DH * TKV;   // transposed [d][tk]

    unsigned uQs = su32(Qs), uKs = su32(Ks), uVs = su32(Vs), uPs = su32(Ps);

    auto loadKV = [&](int buf, int kt) {
        const float* kb = kb0 + (size_t)kt * 64 * DH;
        const float* vb = vb0 + (size_t)kt * 64;       // column offset in tk
        float* Kd = Ks + buf * 64 * 68;
        float* Vd = Vs + buf * 64 * 68;
#pragma unroll
        for (int i = 0; i < 4; i++) {
            int id = tid + i * 256;
            int row = id >> 4, c4 = (id & 15) << 2;
            cpa16(Kd + row * 68 + c4, kb + row * DH + c4);
            cpa16(Vd + row * 68 + c4, vb + (size_t)row * TKV + c4);
        }
    };

    // Prologue: group0={Q,KV0}, group1={KV1}, group2={KV2}
#pragma unroll
    for (int i = 0; i < 8; i++) {
        int id = tid + i * 256;
        int row = id >> 4, c4 = (id & 15) << 2;
        cpa16(Qs + row * 68 + c4, qb + row * DH + c4);
    }
    loadKV(0, 0); CPC;
    loadKV(1, 1); CPC;
    loadKV(2, 2); CPC;

    float oacc[8][4];
    float mrow[2] = {-1e30f, -1e30f};
    float lrow[2] = {0.f, 0.f};
#pragma unroll
    for (int nt = 0; nt < 8; nt++)
#pragma unroll
        for (int c = 0; c < 4; c++) oacc[nt][c] = 0.f;

    // Hoist Q fragments (loop-invariant): wait for group0, load once.
    CPW2; __syncthreads();
    unsigned qF[8][4];
#pragma unroll
    for (int d8 = 0; d8 < 8; d8++) {
        int row = r0w + (((l >> 3) & 1) << 3) + (l & 7);
        int col = d8 * 8 + ((l >> 4) << 2);
        ldsm4(qF[d8], uQs + (unsigned)(row * 68 + col) * 4u);
    }

    int buf = 0;
    for (int kt = 0; kt < nkt; kt++) {
        CPW2; __syncthreads();
        unsigned kbase = uKs + (unsigned)(buf * 64 * 68) * 4u;
        unsigned vbase = uVs + (unsigned)(buf * 64 * 68) * 4u;

        // ---- S = Q @ K^T ----
        float sacc[8][4];
#pragma unroll
        for (int nt = 0; nt < 8; nt++)
#pragma unroll
            for (int c = 0; c < 4; c++) sacc[nt][c] = 0.f;

        unsigned aF[4], bF[4];
#pragma unroll
        for (int d8 = 0; d8 < 8; d8++) {
#pragma unroll
            for (int ntp = 0; ntp < 4; ntp++) {
                int row = ntp * 16 + ((l >> 4) << 3) + (l & 7);
                int col = d8 * 8 + (((l >> 3) & 1) << 2);
                ldsm4(bF, kbase + (unsigned)(row * 68 + col) * 4u);
                mma8(sacc[2 * ntp], qF[d8], bF[0], bF[1]);
                mma8(sacc[2 * ntp + 1], qF[d8], bF[2], bF[3]);
            }
        }

        // ---- causal mask (only near the frontier) ----
        int thresh = q0 + 2048 - kt * 64;
        if (thresh < 64) {
            int rbase = r0w + lg;
#pragma unroll
            for (int nt = 0; nt < 8; nt++) {
                int jj0 = nt * 8 + 2 * lt;
#pragma unroll
                for (int cr = 0; cr < 4; cr++) {
                    int r = rbase + ((cr >> 1) << 3);
                    int jj = jj0 + (cr & 1);
                    if (jj > r + thresh) sacc[nt][cr] = -1e30f;
                }
            }
        }

        // ---- online softmax (warp-local, quad reduce) ----
#pragma unroll
        for (int g = 0; g < 2; g++) {
            float mx = -1e30f;
#pragma unroll
            for (int nt = 0; nt < 8; nt++)
                mx = fmaxf(mx, fmaxf(sacc[nt][2 * g], sacc[nt][2 * g + 1]));
            mx = fmaxf(mx, __shfl_xor_sync(0xffffffffu, mx, 1));
            mx = fmaxf(mx, __shfl_xor_sync(0xffffffffu, mx, 2));
            float mnew = fmaxf(mrow[g], mx);
            float alpha = ex2((mrow[g] - mnew) * FL_C2);
            mrow[g] = mnew;
            float sum = 0.f;
#pragma unroll
            for (int nt = 0; nt < 8; nt++) {
#pragma unroll
                for (int c = 0; c < 2; c++) {
                    float p = ex2((sacc[nt][2 * g + c] - mnew) * FL_C2);
                    sacc[nt][2 * g + c] = p;
                    sum += p;
                }
            }
            sum += __shfl_xor_sync(0xffffffffu, sum, 1);
            sum += __shfl_xor_sync(0xffffffffu, sum, 2);
            lrow[g] = lrow[g] * alpha + sum;
#pragma unroll
            for (int nt = 0; nt < 8; nt++) {
                oacc[nt][2 * g] *= alpha;
                oacc[nt][2 * g + 1] *= alpha;
            }
        }

        // ---- store P (tf32-rounded), warp-private rows ----
#pragma unroll
        for (int g = 0; g < 2; g++) {
            int row = r0w + lg + 8 * g;
#pragma unroll
            for (int nt = 0; nt < 8; nt++) {
                *(float2*)(Ps + row * 68 + nt * 8 + 2 * lt) =
                    make_float2(tfr(sacc[nt][2 * g]), tfr(sacc[nt][2 * g + 1]));
            }
        }
        __syncwarp();

        // ---- O += P @ V  (V d-major: same LDSM pattern as K) ----
#pragma unroll
        for (int k8 = 0; k8 < 8; k8++) {
            {
                int row = r0w + (((l >> 3) & 1) << 3) + (l & 7);
                int col = k8 * 8 + ((l >> 4) << 2);
                ldsm4(aF, uPs + (unsigned)(row * 68 + col) * 4u);
            }
#pragma unroll
            for (int ntp = 0; ntp < 4; ntp++) {
                int row = ntp * 16 + ((l >> 4) << 3) + (l & 7);
                int col = k8 * 8 + (((l >> 3) & 1) << 2);
                ldsm4(bF, vbase + (unsigned)(row * 68 + col) * 4u);
                mma8(oacc[2 * ntp], aF, bF[0], bF[1]);
                mma8(oacc[2 * ntp + 1], aF, bF[2], bF[3]);
            }
        }

        __syncthreads();
        if (kt + 3 < nkt) loadKV(buf, kt + 3);
        CPC;   // empty commits near the tail keep wait_group arithmetic exact
        buf = (buf == 2) ? 0 : buf + 1;
    }

    // ---- epilogue: O/l -> g_attn[b, t, h*64+d] (tf32-rounded) ----
#pragma unroll
    for (int g = 0; g < 2; g++) {
        float inv = 1.f / lrow[g];
        int rg = q0 + r0w + lg + 8 * g;
        float* ob = g_attn + ((size_t)b * TQ + rg) * CM + h * DH;
#pragma unroll
        for (int nt = 0; nt < 8; nt++) {
            *(float2*)(ob + nt * 8 + 2 * lt) =
                make_float2(tfr(oacc[nt][2 * g] * inv),
                            tfr(oacc[nt][2 * g + 1] * inv));
        }
    }
}

// ---------------------------------------------------------------------------
extern "C" void kernel_launch(void* const* d_in, const int* in_sizes, int n_in,
                              void* d_out, int out_size) {
    const float* x  = (const float*)d_in[0];
    const float* kc = (const float*)d_in[1];
    const float* vc = (const float*)d_in[2];
    const float* Wq = (const float*)d_in[3];
    const float* bq = (const float*)d_in[4];
    const float* Wk = (const float*)d_in[5];
    const float* bk = (const float*)d_in[6];
    const float* Wv = (const float*)d_in[7];
    const float* bv = (const float*)d_in[8];
    const float* Wo = (const float*)d_in[9];
    const float* bo = (const float*)d_in[10];
    float* out = (float*)d_out;
    (void)in_sizes; (void)n_in;

    int tail = (out_size >= OUT_ELEMS + 2 * KV_ELEMS);

    cudaFuncSetAttribute(flash_mma_kernel,
                         cudaFuncAttributeMaxDynamicSharedMemorySize, FLASH_SMEM);
    cudaFuncSetAttribute(mma_gemm_kernel<1, 1>,
                         cudaFuncAttributeMaxDynamicSharedMemorySize, GEMM_SMEM);
    cudaFuncSetAttribute(mma_gemm_kernel<1, 0>,
                         cudaFuncAttributeMaxDynamicSharedMemorySize, GEMM_SMEM);
    cudaFuncSetAttribute(mma_gemm_kernel<0, 0>,
                         cudaFuncAttributeMaxDynamicSharedMemorySize, GEMM_SMEM);

    {
        int total4 = BB * NH * 2048 * DH / 4;
        int nb = (total4 + 255) / 256;
        if (tail)
            copy_cache_kernel<1><<<nb, 256>>>(
                (const float4*)kc, (const float4*)vc,
                (float4*)(out + OUT_ELEMS), (float4*)(out + OUT_ELEMS + KV_ELEMS));
        else
            copy_cache_kernel<0><<<nb, 256>>>(
                (const float4*)kc, (const float4*)vc, nullptr, nullptr);
    }
    transpose_vcache_kernel<<<dim3(64, 2, BB * NH), dim3(32, 8)>>>(vc);
    {
        int n4 = (OUT_ELEMS + 4 * CM * CM) / 4;
        round_inputs_kernel<<<(n4 + 255) / 256, 256>>>(
            (const float4*)x, (const float4*)Wq, (const float4*)Wk,
            (const float4*)Wv, (const float4*)Wo);
    }

    // Fused QKV projection: one launch, 768 CTAs
    dim3 qkvgrid(24, (BB * TQ) / 128);
    if (tail)
        mma_gemm_kernel<1, 1><<<qkvgrid, 256, GEMM_SMEM>>>(
            bq, bk, bv, out + OUT_ELEMS);
    else
        mma_gemm_kernel<1, 0><<<qkvgrid, 256, GEMM_SMEM>>>(
            bq, bk, bv, nullptr);

    flash_mma_kernel<<<dim3(TQ / 128, NH, BB), 256, FLASH_SMEM>>>();

    mma_gemm_kernel<0, 0><<<dim3(CM / 128, (BB * TQ) / 128), 256, GEMM_SMEM>>>(
        bo, nullptr, nullptr, out);
}

// round 12
// speedup vs baseline: 3.9379x; 1.1369x over previous
#include <cuda_runtime.h>
#include <math.h>
#include <float.h>

// Problem dims
#define BB   2
#define TQ   2048
#define CM   1024
#define NH   16
#define DH   64
#define TKV  4096
#define OUT_ELEMS (BB*TQ*CM)            // 4194304
#define KV_ELEMS  (BB*NH*TKV*DH)        // 8388608

// Scratch (device globals; allocation-free)
__device__ __align__(16) float g_q[BB*NH*TQ*DH];    // [b,h,t,d]  tf32-rounded
__device__ __align__(16) float g_kf[KV_ELEMS];      // [b,h,tk,d]
__device__ __align__(16) float g_vf[KV_ELEMS];      // [b,h,d,tk]  TRANSPOSED
__device__ __align__(16) float g_attn[OUT_ELEMS];   // [b,t,c]    tf32-rounded
__device__ __align__(16) float g_xr[OUT_ELEMS];     // x rounded to tf32
__device__ __align__(16) float g_wr[4*CM*CM];       // Wq,Wk,Wv,Wo rounded

// ---------------------------------------------------------------------------
// PTX helpers
// ---------------------------------------------------------------------------
__device__ __forceinline__ unsigned su32(const void* p) {
    return (unsigned)__cvta_generic_to_shared(p);
}
__device__ __forceinline__ void cpa16(void* d, const void* s) {
    asm volatile("cp.async.cg.shared.global [%0], [%1], 16;"
                 :: "r"(su32(d)), "l"(s));
}
#define CPC  asm volatile("cp.async.commit_group;")
#define CPW1 asm volatile("cp.async.wait_group 1;")
#define CPW2 asm volatile("cp.async.wait_group 2;")

__device__ __forceinline__ void ldsm4(unsigned* r, unsigned a) {
    asm volatile("ldmatrix.sync.aligned.m8n8.x4.shared.b16 {%0,%1,%2,%3}, [%4];"
                 : "=r"(r[0]), "=r"(r[1]), "=r"(r[2]), "=r"(r[3]) : "r"(a));
}
__device__ __forceinline__ void mma8(float* c, const unsigned* a,
                                     unsigned b0, unsigned b1) {
    asm volatile(
        "mma.sync.aligned.m16n8k8.row.col.f32.tf32.tf32.f32 "
        "{%0,%1,%2,%3}, {%4,%5,%6,%7}, {%8,%9}, {%0,%1,%2,%3};\n"
        : "+f"(c[0]), "+f"(c[1]), "+f"(c[2]), "+f"(c[3])
        : "r"(a[0]), "r"(a[1]), "r"(a[2]), "r"(a[3]), "r"(b0), "r"(b1));
}
__device__ __forceinline__ float tfr(float x) {   // round-to-nearest tf32
    unsigned u;
    asm("cvt.rna.tf32.f32 %0, %1;" : "=r"(u) : "f"(x));
    return __uint_as_float(u);
}
__device__ __forceinline__ float ex2(float x) {
    float y; asm("ex2.approx.f32 %0, %1;" : "=f"(y) : "f"(x)); return y;
}

// ---------------------------------------------------------------------------
// Pre-pass: round x and the 4 weight matrices to tf32 (rna)
// ---------------------------------------------------------------------------
__global__ void round_inputs_kernel(const float4* __restrict__ x,
                                    const float4* __restrict__ wq,
                                    const float4* __restrict__ wk,
                                    const float4* __restrict__ wv,
                                    const float4* __restrict__ wo) {
    int i = blockIdx.x * blockDim.x + threadIdx.x;
    const int NX = OUT_ELEMS / 4;
    const int NW = (CM * CM) / 4;
    float4 v; float4* dst;
    if (i < NX) {
        v = x[i]; dst = (float4*)g_xr + i;
    } else {
        int j = i - NX;
        if (j >= 4 * NW) return;
        int ws = j / NW, off = j - ws * NW;
        const float4* src = (ws == 0) ? wq : (ws == 1) ? wk : (ws == 2) ? wv : wo;
        v = src[off];
        dst = (float4*)g_wr + (size_t)ws * NW + off;
    }
    v.x = tfr(v.x); v.y = tfr(v.y); v.z = tfr(v.z); v.w = tfr(v.w);
    *dst = v;
}

// ---------------------------------------------------------------------------
// Copy k cache into rows [0,2048) of g_kf + exact k/v tails to output
// ---------------------------------------------------------------------------
template <int TAIL>
__global__ void copy_cache_kernel(const float4* __restrict__ kc,
                                  const float4* __restrict__ vc,
                                  float4* __restrict__ out_k,
                                  float4* __restrict__ out_v) {
    int idx = blockIdx.x * blockDim.x + threadIdx.x;
    const int total4 = BB * NH * 2048 * DH / 4;
    if (idx >= total4) return;
    int e  = idx << 2;
    int d  = e & (DH - 1);
    int t  = (e >> 6) & 2047;
    int bh = e >> 17;
    int dst4 = (((bh * TKV) + t) * DH + d) >> 2;
    float4 kv = kc[idx];
    ((float4*)g_kf)[dst4] = kv;
    if (TAIL) { out_k[dst4] = kv; out_v[dst4] = vc[idx]; }
}

// ---------------------------------------------------------------------------
// Transpose v cache [bh][t][d] -> g_vf [bh][d][t]  (t in [0,2048))
// ---------------------------------------------------------------------------
__global__ void transpose_vcache_kernel(const float* __restrict__ vc) {
    __shared__ float tile[32][33];
    int bh = blockIdx.z;
    int c0 = blockIdx.x * 32, d0 = blockIdx.y * 32;
    int tx = threadIdx.x, ty = threadIdx.y;   // 32 x 8
    const float* src = vc + ((size_t)bh * 2048 + c0) * DH + d0;
#pragma unroll
    for (int j = 0; j < 32; j += 8)
        tile[ty + j][tx] = src[(size_t)(ty + j) * DH + tx];
    __syncthreads();
    float* dst = g_vf + ((size_t)bh * DH + d0) * TKV + c0;
#pragma unroll
    for (int j = 0; j < 32; j += 8)
        dst[(size_t)(ty + j) * TKV + tx] = tile[tx][ty + j];
}

// ---------------------------------------------------------------------------
// tf32 tensor-core GEMM: 128x128 tile, kc=16, 3-stage cp.async pipeline.
// Bs padded to 136 (stride mod 32 = 8) -> conflict-free B scalar loads.
// ---------------------------------------------------------------------------
#define GEMM_SMEM ((3*128*20 + 3*16*136) * 4)   // 56832 B

template <int MODE, int TAIL>
__global__ void __launch_bounds__(256, 2)
mma_gemm_kernel(const float* __restrict__ b0p, const float* __restrict__ b1p,
                const float* __restrict__ b2p, float* __restrict__ Cout) {
    extern __shared__ float gsm[];
    float* As = gsm;                 // [3][128][20]
    float* Bs = gsm + 3 * 128 * 20;  // [3][16][136]

    int sec, n0;
    const float* Ap; const float* Wp; const float* bias;
    if (MODE == 0) {
        Ap = g_attn; Wp = g_wr + (size_t)3 * CM * CM; bias = b0p;
        n0 = blockIdx.x * 128; sec = 0;
    } else {
        Ap = g_xr;
        sec = blockIdx.x >> 3;
        n0 = (blockIdx.x & 7) * 128;
        Wp = g_wr + (size_t)sec * CM * CM;
        bias = (sec == 0) ? b0p : (sec == 1) ? b1p : b2p;
    }

    int tid = threadIdx.x;
    int w = tid >> 5, l = tid & 31, lg = l >> 2, lt = l & 3;
    int wm = w & 3, wn = w >> 2;
    int m0 = blockIdx.y * 128;

    auto loadAB = [&](int buf, int kt) {
        int k0 = kt * 16;
        float* Ad = As + buf * 2560;
        float* Bd = Bs + buf * 2176;
#pragma unroll
        for (int i = 0; i < 2; i++) {
            int id = tid + i * 256;
            int row = id >> 2, c4 = (id & 3) << 2;
            cpa16(Ad + row * 20 + c4, Ap + (size_t)(m0 + row) * CM + k0 + c4);
            int kr = id >> 5, c = (id & 31) << 2;
            cpa16(Bd + kr * 136 + c, Wp + (size_t)(k0 + kr) * CM + n0 + c);
        }
    };

    float acc[2][8][4];
#pragma unroll
    for (int mt = 0; mt < 2; mt++)
#pragma unroll
        for (int nt = 0; nt < 8; nt++)
#pragma unroll
            for (int c = 0; c < 4; c++) acc[mt][nt][c] = 0.f;

    unsigned uAs = su32(As);

    loadAB(0, 0); CPC;
    loadAB(1, 1); CPC;
    loadAB(2, 2); CPC;

    int buf = 0;
    for (int kt = 0; kt < CM / 16; kt++) {
        CPW2; __syncthreads();
        const float* Bb = Bs + buf * 2176;
#pragma unroll
        for (int ks = 0; ks < 2; ks++) {
            unsigned aF[2][4];
#pragma unroll
            for (int mt = 0; mt < 2; mt++) {
                int row = wm * 32 + mt * 16 + (((l >> 3) & 1) << 3) + (l & 7);
                int col = ks * 8 + ((l >> 4) << 2);
                ldsm4(aF[mt], uAs + (unsigned)(buf * 2560 + row * 20 + col) * 4u);
            }
#pragma unroll
            for (int nt = 0; nt < 8; nt++) {
                int k = ks * 8 + lt;
                int n = wn * 64 + nt * 8 + lg;
                unsigned b0 = __float_as_uint(Bb[k * 136 + n]);
                unsigned b1 = __float_as_uint(Bb[(k + 4) * 136 + n]);
                mma8(acc[0][nt], aF[0], b0, b1);
                mma8(acc[1][nt], aF[1], b0, b1);
            }
        }
        __syncthreads();
        if (kt + 3 < CM / 16) loadAB(buf, kt + 3);
        CPC;   // empty commits near the tail keep wait_group arithmetic exact
        buf = (buf == 2) ? 0 : buf + 1;
    }

    // Epilogue
#pragma unroll
    for (int mt = 0; mt < 2; mt++)
#pragma unroll
        for (int nt = 0; nt < 8; nt++)
#pragma unroll
            for (int g = 0; g < 2; g++) {
                int m = m0 + wm * 32 + mt * 16 + lg + 8 * g;
                int n = n0 + wn * 64 + nt * 8 + 2 * lt;
                float v0 = acc[mt][nt][2 * g] + bias[n];
                float v1 = acc[mt][nt][2 * g + 1] + bias[n + 1];
                if (MODE == 0) {
                    *(float2*)&Cout[(size_t)m * CM + n] = make_float2(v0, v1);
                } else {
                    int b = m >> 11, t = m & 2047;
                    int h = n >> 6, d = n & 63;
                    int bh = b * NH + h;
                    if (sec == 0) {
                        size_t off = ((size_t)bh * TQ + t) * DH + d;
                        *(float2*)(g_q + off) = make_float2(tfr(v0), tfr(v1));
                    } else if (sec == 1) {
                        size_t off = ((size_t)bh * TKV + 2048 + t) * DH + d;
                        *(float2*)(g_kf + off) = make_float2(tfr(v0), tfr(v1));
                        if (TAIL)
                            *(float2*)(Cout + off) = make_float2(v0, v1);
                    } else {
                        size_t offT = ((size_t)bh * DH + d) * TKV + 2048 + t;
                        g_vf[offT]       = tfr(v0);
                        g_vf[offT + TKV] = tfr(v1);
                        if (TAIL) {
                            size_t off = ((size_t)bh * TKV + 2048 + t) * DH + d;
                            *(float2*)(Cout + KV_ELEMS + off) = make_float2(v0, v1);
                        }
                    }
                }
            }
}

// ---------------------------------------------------------------------------
// tf32 flash attention, 128-thread CTAs (Bq=64, 4 warps x 16 q-rows),
// 2-stage K/V cp.async, 3 CTAs/SM. Q fragments via direct LDG (no Qs),
// P kept in registers and quad-shuffled into the PV A-fragment (no Ps).
// ---------------------------------------------------------------------------
#define FL_C2 0.1803368801111f   /* 0.125 * log2(e) */
#define FLASH_SMEM (2 * (2*64*68) * 4)   // K + V, 2 stages: 69632 B

__global__ void __launch_bounds__(128, 3) flash_mma_kernel() {
    extern __shared__ float fsm[];
    float* Ks = fsm;                    // [2][64][68]  (c-major: Ks[c][d])
    float* Vs = fsm + 2 * 64 * 68;      // [2][64][68]  (d-major: Vs[d][c])

    int qt = 31 - blockIdx.x;           // heavy tiles first
    int h = blockIdx.y, b = blockIdx.z;
    int bh = b * NH + h;
    int q0 = qt * 64;
    int nkt = qt + 33;

    int tid = threadIdx.x;
    int w = tid >> 5, l = tid & 31, lg = l >> 2, lt = l & 3;
    int r0w = w * 16;

    const float* kb0 = g_kf + (size_t)bh * TKV * DH;
    const float* vb0 = g_vf + (size_t)bh * DH * TKV;   // transposed [d][tk]

    unsigned uKs = su32(Ks), uVs = su32(Vs);

    auto loadKV = [&](int buf, int kt) {
        const float* kb = kb0 + (size_t)kt * 64 * DH;
        const float* vb = vb0 + (size_t)kt * 64;
        float* Kd = Ks + buf * 64 * 68;
        float* Vd = Vs + buf * 64 * 68;
#pragma unroll
        for (int i = 0; i < 8; i++) {
            int id = tid + i * 128;
            int row = id >> 4, c4 = (id & 15) << 2;
            cpa16(Kd + row * 68 + c4, kb + row * DH + c4);
            cpa16(Vd + row * 68 + c4, vb + (size_t)row * TKV + c4);
        }
    };

    loadKV(0, 0); CPC;
    loadKV(1, 1); CPC;

    // Q fragments straight from gmem (g_q already tf32-rounded).
    // A-frag: {a0,a1,a2,a3} = {Q[r][c], Q[r+8][c], Q[r][c+4], Q[r+8][c+4]},
    // r = q0 + r0w + lg, c = d8*8 + lt.
    unsigned qF[8][4];
    {
        const float* q0p = g_q + ((size_t)bh * TQ + q0 + r0w + lg) * DH;
        const float* q8p = q0p + 8 * DH;
#pragma unroll
        for (int d8 = 0; d8 < 8; d8++) {
            int c = d8 * 8 + lt;
            qF[d8][0] = __float_as_uint(q0p[c]);
            qF[d8][1] = __float_as_uint(q8p[c]);
            qF[d8][2] = __float_as_uint(q0p[c + 4]);
            qF[d8][3] = __float_as_uint(q8p[c + 4]);
        }
    }

    float oacc[8][4];
    float mrow[2] = {-1e30f, -1e30f};
    float lrow[2] = {0.f, 0.f};
#pragma unroll
    for (int nt = 0; nt < 8; nt++)
#pragma unroll
        for (int c = 0; c < 4; c++) oacc[nt][c] = 0.f;

    int srcA = (l & 28) | (lt >> 1);   // 4*lg + lt/2
    int srcB = srcA + 2;
    bool odd = (lt & 1);

    int buf = 0;
    for (int kt = 0; kt < nkt; kt++) {
        CPW1; __syncthreads();
        unsigned kbase = uKs + (unsigned)(buf * 64 * 68) * 4u;
        unsigned vbase = uVs + (unsigned)(buf * 64 * 68) * 4u;

        // ---- S = Q @ K^T ----
        float sacc[8][4];
#pragma unroll
        for (int nt = 0; nt < 8; nt++)
#pragma unroll
            for (int c = 0; c < 4; c++) sacc[nt][c] = 0.f;

        unsigned bF[4];
#pragma unroll
        for (int d8 = 0; d8 < 8; d8++) {
#pragma unroll
            for (int ntp = 0; ntp < 4; ntp++) {
                int row = ntp * 16 + ((l >> 4) << 3) + (l & 7);
                int col = d8 * 8 + (((l >> 3) & 1) << 2);
                ldsm4(bF, kbase + (unsigned)(row * 68 + col) * 4u);
                mma8(sacc[2 * ntp], qF[d8], bF[0], bF[1]);
                mma8(sacc[2 * ntp + 1], qF[d8], bF[2], bF[3]);
            }
        }

        // ---- causal mask (only near the frontier) ----
        int thresh = q0 + 2048 - kt * 64;
        if (thresh < 64) {
            int rbase = r0w + lg;
#pragma unroll
            for (int nt = 0; nt < 8; nt++) {
                int jj0 = nt * 8 + 2 * lt;
#pragma unroll
                for (int cr = 0; cr < 4; cr++) {
                    int r = rbase + ((cr >> 1) << 3);
                    int jj = jj0 + (cr & 1);
                    if (jj > r + thresh) sacc[nt][cr] = -1e30f;
                }
            }
        }

        // ---- online softmax (warp-local, quad reduce) ----
#pragma unroll
        for (int g = 0; g < 2; g++) {
            float mx = -1e30f;
#pragma unroll
            for (int nt = 0; nt < 8; nt++)
                mx = fmaxf(mx, fmaxf(sacc[nt][2 * g], sacc[nt][2 * g + 1]));
            mx = fmaxf(mx, __shfl_xor_sync(0xffffffffu, mx, 1));
            mx = fmaxf(mx, __shfl_xor_sync(0xffffffffu, mx, 2));
            float mnew = fmaxf(mrow[g], mx);
            float alpha = ex2((mrow[g] - mnew) * FL_C2);
            mrow[g] = mnew;
            float sum = 0.f;
#pragma unroll
            for (int nt = 0; nt < 8; nt++) {
#pragma unroll
                for (int c = 0; c < 2; c++) {
                    float p = ex2((sacc[nt][2 * g + c] - mnew) * FL_C2);
                    sacc[nt][2 * g + c] = p;
                    sum += p;
                }
            }
            sum += __shfl_xor_sync(0xffffffffu, sum, 1);
            sum += __shfl_xor_sync(0xffffffffu, sum, 2);
            lrow[g] = lrow[g] * alpha + sum;
#pragma unroll
            for (int nt = 0; nt < 8; nt++) {
                oacc[nt][2 * g] *= alpha;
                oacc[nt][2 * g + 1] *= alpha;
            }
        }

        // ---- round P to tf32 (same values the old STS/LDSM path fed) ----
#pragma unroll
        for (int nt = 0; nt < 8; nt++)
#pragma unroll
            for (int c = 0; c < 4; c++) sacc[nt][c] = tfr(sacc[nt][c]);

        // ---- O += P @ V : P shuffled into A-fragments, V via LDSM ----
#pragma unroll
        for (int k8 = 0; k8 < 8; k8++) {
            float sA0 = __shfl_sync(0xffffffffu, sacc[k8][0], srcA);
            float sA1 = __shfl_sync(0xffffffffu, sacc[k8][1], srcA);
            float sA2 = __shfl_sync(0xffffffffu, sacc[k8][2], srcA);
            float sA3 = __shfl_sync(0xffffffffu, sacc[k8][3], srcA);
            float sB0 = __shfl_sync(0xffffffffu, sacc[k8][0], srcB);
            float sB1 = __shfl_sync(0xffffffffu, sacc[k8][1], srcB);
            float sB2 = __shfl_sync(0xffffffffu, sacc[k8][2], srcB);
            float sB3 = __shfl_sync(0xffffffffu, sacc[k8][3], srcB);
            unsigned aF[4];
            aF[0] = __float_as_uint(odd ? sA1 : sA0);  // P[lg][k8*8+lt]
            aF[1] = __float_as_uint(odd ? sA3 : sA2);  // P[lg+8][k8*8+lt]
            aF[2] = __float_as_uint(odd ? sB1 : sB0);  // P[lg][k8*8+lt+4]
            aF[3] = __float_as_uint(odd ? sB3 : sB2);  // P[lg+8][k8*8+lt+4]
#pragma unroll
            for (int ntp = 0; ntp < 4; ntp++) {
                int row = ntp * 16 + ((l >> 4) << 3) + (l & 7);
                int col = k8 * 8 + (((l >> 3) & 1) << 2);
                ldsm4(bF, vbase + (unsigned)(row * 68 + col) * 4u);
                mma8(oacc[2 * ntp], aF, bF[0], bF[1]);
                mma8(oacc[2 * ntp + 1], aF, bF[2], bF[3]);
            }
        }

        __syncthreads();
        if (kt + 2 < nkt) loadKV(buf, kt + 2);
        CPC;   // empty commits near the tail keep wait_group arithmetic exact
        buf ^= 1;
    }

    // ---- epilogue: O/l -> g_attn[b, t, h*64+d] (tf32-rounded) ----
#pragma unroll
    for (int g = 0; g < 2; g++) {
        float inv = 1.f / lrow[g];
        int rg = q0 + r0w + lg + 8 * g;
        float* ob = g_attn + ((size_t)b * TQ + rg) * CM + h * DH;
#pragma unroll
        for (int nt = 0; nt < 8; nt++) {
            *(float2*)(ob + nt * 8 + 2 * lt) =
                make_float2(tfr(oacc[nt][2 * g] * inv),
                            tfr(oacc[nt][2 * g + 1] * inv));
        }
    }
}

// ---------------------------------------------------------------------------
extern "C" void kernel_launch(void* const* d_in, const int* in_sizes, int n_in,
                              void* d_out, int out_size) {
    const float* x  = (const float*)d_in[0];
    const float* kc = (const float*)d_in[1];
    const float* vc = (const float*)d_in[2];
    const float* Wq = (const float*)d_in[3];
    const float* bq = (const float*)d_in[4];
    const float* Wk = (const float*)d_in[5];
    const float* bk = (const float*)d_in[6];
    const float* Wv = (const float*)d_in[7];
    const float* bv = (const float*)d_in[8];
    const float* Wo = (const float*)d_in[9];
    const float* bo = (const float*)d_in[10];
    float* out = (float*)d_out;
    (void)in_sizes; (void)n_in;

    int tail = (out_size >= OUT_ELEMS + 2 * KV_ELEMS);

    cudaFuncSetAttribute(flash_mma_kernel,
                         cudaFuncAttributeMaxDynamicSharedMemorySize, FLASH_SMEM);
    cudaFuncSetAttribute(mma_gemm_kernel<1, 1>,
                         cudaFuncAttributeMaxDynamicSharedMemorySize, GEMM_SMEM);
    cudaFuncSetAttribute(mma_gemm_kernel<1, 0>,
                         cudaFuncAttributeMaxDynamicSharedMemorySize, GEMM_SMEM);
    cudaFuncSetAttribute(mma_gemm_kernel<0, 0>,
                         cudaFuncAttributeMaxDynamicSharedMemorySize, GEMM_SMEM);

    {
        int total4 = BB * NH * 2048 * DH / 4;
        int nb = (total4 + 255) / 256;
        if (tail)
            copy_cache_kernel<1><<<nb, 256>>>(
                (const float4*)kc, (const float4*)vc,
                (float4*)(out + OUT_ELEMS), (float4*)(out + OUT_ELEMS + KV_ELEMS));
        else
            copy_cache_kernel<0><<<nb, 256>>>(
                (const float4*)kc, (const float4*)vc, nullptr, nullptr);
    }
    transpose_vcache_kernel<<<dim3(64, 2, BB * NH), dim3(32, 8)>>>(vc);
    {
        int n4 = (OUT_ELEMS + 4 * CM * CM) / 4;
        round_inputs_kernel<<<(n4 + 255) / 256, 256>>>(
            (const float4*)x, (const float4*)Wq, (const float4*)Wk,
            (const float4*)Wv, (const float4*)Wo);
    }

    // Fused QKV projection: one launch, 768 CTAs
    dim3 qkvgrid(24, (BB * TQ) / 128);
    if (tail)
        mma_gemm_kernel<1, 1><<<qkvgrid, 256, GEMM_SMEM>>>(
            bq, bk, bv, out + OUT_ELEMS);
    else
        mma_gemm_kernel<1, 0><<<qkvgrid, 256, GEMM_SMEM>>>(
            bq, bk, bv, nullptr);

    flash_mma_kernel<<<dim3(TQ / 64, NH, BB), 128, FLASH_SMEM>>>();

    mma_gemm_kernel<0, 0><<<dim3(CM / 128, (BB * TQ) / 128), 256, GEMM_SMEM>>>(
        bo, nullptr, nullptr, out);
}

// round 13
// speedup vs baseline: 3.9893x; 1.0131x over previous
#include <cuda_runtime.h>
#include <math.h>
#include <float.h>

// Problem dims
#define BB   2
#define TQ   2048
#define CM   1024
#define NH   16
#define DH   64
#define TKV  4096
#define OUT_ELEMS (BB*TQ*CM)            // 4194304
#define KV_ELEMS  (BB*NH*TKV*DH)        // 8388608

// Scratch (device globals; allocation-free)
__device__ __align__(16) float g_q[BB*NH*TQ*DH];    // [b,h,t,d]  tf32-rounded
__device__ __align__(16) float g_kf[KV_ELEMS];      // [b,h,tk,d]
__device__ __align__(16) float g_vf[KV_ELEMS];      // [b,h,d,tk]  TRANSPOSED
__device__ __align__(16) float g_attn[OUT_ELEMS];   // [b,t,c]    tf32-rounded
__device__ __align__(16) float g_xr[OUT_ELEMS];     // x rounded to tf32
__device__ __align__(16) float g_wr[4*CM*CM];       // Wq,Wk,Wv,Wo rounded

// ---------------------------------------------------------------------------
// PTX helpers
// ---------------------------------------------------------------------------
__device__ __forceinline__ unsigned su32(const void* p) {
    return (unsigned)__cvta_generic_to_shared(p);
}
__device__ __forceinline__ void cpa16(void* d, const void* s) {
    asm volatile("cp.async.cg.shared.global [%0], [%1], 16;"
                 :: "r"(su32(d)), "l"(s));
}
#define CPC  asm volatile("cp.async.commit_group;")
#define CPW1 asm volatile("cp.async.wait_group 1;")
#define CPW2 asm volatile("cp.async.wait_group 2;")

__device__ __forceinline__ void ldsm4(unsigned* r, unsigned a) {
    asm volatile("ldmatrix.sync.aligned.m8n8.x4.shared.b16 {%0,%1,%2,%3}, [%4];"
                 : "=r"(r[0]), "=r"(r[1]), "=r"(r[2]), "=r"(r[3]) : "r"(a));
}
__device__ __forceinline__ void mma8(float* c, const unsigned* a,
                                     unsigned b0, unsigned b1) {
    asm volatile(
        "mma.sync.aligned.m16n8k8.row.col.f32.tf32.tf32.f32 "
        "{%0,%1,%2,%3}, {%4,%5,%6,%7}, {%8,%9}, {%0,%1,%2,%3};\n"
        : "+f"(c[0]), "+f"(c[1]), "+f"(c[2]), "+f"(c[3])
        : "r"(a[0]), "r"(a[1]), "r"(a[2]), "r"(a[3]), "r"(b0), "r"(b1));
}
__device__ __forceinline__ float tfr(float x) {   // round-to-nearest tf32
    unsigned u;
    asm("cvt.rna.tf32.f32 %0, %1;" : "=r"(u) : "f"(x));
    return __uint_as_float(u);
}
__device__ __forceinline__ float ex2(float x) {
    float y; asm("ex2.approx.f32 %0, %1;" : "=f"(y) : "f"(x)); return y;
}

// ---------------------------------------------------------------------------
// Fused pre-pass: one launch, block-range dispatch.
//   blocks [0, 4096):        copy kv cache rows into g_kf (+ exact out tails)
//   blocks [4096, 12288):    round x and the 4 weight matrices to tf32
//   blocks [12288, 16384):   transpose v cache [bh][t][d] -> g_vf [bh][d][t]
// ---------------------------------------------------------------------------
#define PREPASS_BLOCKS 16384

template <int TAIL>
__global__ void __launch_bounds__(256) prepass_kernel(
    const float4* __restrict__ x,
    const float4* __restrict__ kc, const float4* __restrict__ vc,
    const float4* __restrict__ wq, const float4* __restrict__ wk,
    const float4* __restrict__ wv, const float4* __restrict__ wo,
    const float* __restrict__ vcf,
    float4* __restrict__ out_k, float4* __restrict__ out_v) {
    __shared__ float tile[32][33];
    int blk = blockIdx.x;
    if (blk < 4096) {
        // --- kv cache copy (1048576 float4) ---
        int idx = blk * 256 + threadIdx.x;
        int e  = idx << 2;
        int d  = e & (DH - 1);
        int t  = (e >> 6) & 2047;
        int bh = e >> 17;
        int dst4 = (((bh * TKV) + t) * DH + d) >> 2;
        float4 kv = kc[idx];
        ((float4*)g_kf)[dst4] = kv;
        if (TAIL) { out_k[dst4] = kv; out_v[dst4] = vc[idx]; }
    } else if (blk < 12288) {
        // --- tf32 rounding (2097152 float4) ---
        int i = (blk - 4096) * 256 + threadIdx.x;
        const int NX = OUT_ELEMS / 4;
        const int NW = (CM * CM) / 4;
        float4 v; float4* dst;
        if (i < NX) {
            v = x[i]; dst = (float4*)g_xr + i;
        } else {
            int j = i - NX;
            int ws = j / NW, off = j - ws * NW;
            const float4* src = (ws == 0) ? wq : (ws == 1) ? wk
                              : (ws == 2) ? wv : wo;
            v = src[off];
            dst = (float4*)g_wr + (size_t)ws * NW + off;
        }
        v.x = tfr(v.x); v.y = tfr(v.y); v.z = tfr(v.z); v.w = tfr(v.w);
        *dst = v;
    } else {
        // --- v cache transpose (4096 32x32 tiles) ---
        int tb = blk - 12288;
        int bh = tb >> 7;
        int rem = tb & 127;
        int c0 = (rem & 63) * 32, d0 = (rem >> 6) * 32;
        int tx = threadIdx.x & 31, ty = threadIdx.x >> 5;   // 32 x 8
        const float* src = vcf + ((size_t)bh * 2048 + c0) * DH + d0;
#pragma unroll
        for (int j = 0; j < 32; j += 8)
            tile[ty + j][tx] = src[(size_t)(ty + j) * DH + tx];
        __syncthreads();
        float* dst = g_vf + ((size_t)bh * DH + d0) * TKV + c0;
#pragma unroll
        for (int j = 0; j < 32; j += 8)
            dst[(size_t)(ty + j) * TKV + tx] = tile[tx][ty + j];
    }
}

// ---------------------------------------------------------------------------
// tf32 tensor-core GEMM: 128x128 tile, kc=16, 4-stage one-sync pipeline.
// Each iteration: wait stage kt; sync (proves kt-1 fully consumed); issue
// loads for kt+3 into slot (kt+3)%4 == (kt-1)%4 (freed last iter); compute.
// Bs padded to 136 -> conflict-free B scalar loads.
// ---------------------------------------------------------------------------
#define GEMM_SMEM ((4*128*20 + 4*16*136) * 4)   // 75776 B

template <int MODE, int TAIL>
__global__ void __launch_bounds__(256, 2)
mma_gemm_kernel(const float* __restrict__ b0p, const float* __restrict__ b1p,
                const float* __restrict__ b2p, float* __restrict__ Cout) {
    extern __shared__ float gsm[];
    float* As = gsm;                 // [4][128][20]
    float* Bs = gsm + 4 * 128 * 20;  // [4][16][136]

    int sec, n0;
    const float* Ap; const float* Wp; const float* bias;
    if (MODE == 0) {
        Ap = g_attn; Wp = g_wr + (size_t)3 * CM * CM; bias = b0p;
        n0 = blockIdx.x * 128; sec = 0;
    } else {
        Ap = g_xr;
        sec = blockIdx.x >> 3;
        n0 = (blockIdx.x & 7) * 128;
        Wp = g_wr + (size_t)sec * CM * CM;
        bias = (sec == 0) ? b0p : (sec == 1) ? b1p : b2p;
    }

    int tid = threadIdx.x;
    int w = tid >> 5, l = tid & 31, lg = l >> 2, lt = l & 3;
    int wm = w & 3, wn = w >> 2;
    int m0 = blockIdx.y * 128;

    auto loadAB = [&](int buf, int kt) {
        int k0 = kt * 16;
        float* Ad = As + buf * 2560;
        float* Bd = Bs + buf * 2176;
#pragma unroll
        for (int i = 0; i < 2; i++) {
            int id = tid + i * 256;
            int row = id >> 2, c4 = (id & 3) << 2;
            cpa16(Ad + row * 20 + c4, Ap + (size_t)(m0 + row) * CM + k0 + c4);
            int kr = id >> 5, c = (id & 31) << 2;
            cpa16(Bd + kr * 136 + c, Wp + (size_t)(k0 + kr) * CM + n0 + c);
        }
    };

    float acc[2][8][4];
#pragma unroll
    for (int mt = 0; mt < 2; mt++)
#pragma unroll
        for (int nt = 0; nt < 8; nt++)
#pragma unroll
            for (int c = 0; c < 4; c++) acc[mt][nt][c] = 0.f;

    unsigned uAs = su32(As);

    loadAB(0, 0); CPC;
    loadAB(1, 1); CPC;
    loadAB(2, 2); CPC;

    const int NKT = CM / 16;   // 64
    for (int kt = 0; kt < NKT; kt++) {
        CPW2; __syncthreads();
        if (kt + 3 < NKT) loadAB((kt + 3) & 3, kt + 3);
        CPC;   // empty commits near the tail keep wait_group arithmetic exact
        int buf = kt & 3;
        const float* Bb = Bs + buf * 2176;
#pragma unroll
        for (int ks = 0; ks < 2; ks++) {
            unsigned aF[2][4];
#pragma unroll
            for (int mt = 0; mt < 2; mt++) {
                int row = wm * 32 + mt * 16 + (((l >> 3) & 1) << 3) + (l & 7);
                int col = ks * 8 + ((l >> 4) << 2);
                ldsm4(aF[mt], uAs + (unsigned)(buf * 2560 + row * 20 + col) * 4u);
            }
#pragma unroll
            for (int nt = 0; nt < 8; nt++) {
                int k = ks * 8 + lt;
                int n = wn * 64 + nt * 8 + lg;
                unsigned b0 = __float_as_uint(Bb[k * 136 + n]);
                unsigned b1 = __float_as_uint(Bb[(k + 4) * 136 + n]);
                mma8(acc[0][nt], aF[0], b0, b1);
                mma8(acc[1][nt], aF[1], b0, b1);
            }
        }
    }

    // Epilogue
#pragma unroll
    for (int mt = 0; mt < 2; mt++)
#pragma unroll
        for (int nt = 0; nt < 8; nt++)
#pragma unroll
            for (int g = 0; g < 2; g++) {
                int m = m0 + wm * 32 + mt * 16 + lg + 8 * g;
                int n = n0 + wn * 64 + nt * 8 + 2 * lt;
                float v0 = acc[mt][nt][2 * g] + bias[n];
                float v1 = acc[mt][nt][2 * g + 1] + bias[n + 1];
                if (MODE == 0) {
                    *(float2*)&Cout[(size_t)m * CM + n] = make_float2(v0, v1);
                } else {
                    int b = m >> 11, t = m & 2047;
                    int h = n >> 6, d = n & 63;
                    int bh = b * NH + h;
                    if (sec == 0) {
                        size_t off = ((size_t)bh * TQ + t) * DH + d;
                        *(float2*)(g_q + off) = make_float2(tfr(v0), tfr(v1));
                    } else if (sec == 1) {
                        size_t off = ((size_t)bh * TKV + 2048 + t) * DH + d;
                        *(float2*)(g_kf + off) = make_float2(tfr(v0), tfr(v1));
                        if (TAIL)
                            *(float2*)(Cout + off) = make_float2(v0, v1);
                    } else {
                        size_t offT = ((size_t)bh * DH + d) * TKV + 2048 + t;
                        g_vf[offT]       = tfr(v0);
                        g_vf[offT + TKV] = tfr(v1);
                        if (TAIL) {
                            size_t off = ((size_t)bh * TKV + 2048 + t) * DH + d;
                            *(float2*)(Cout + KV_ELEMS + off) = make_float2(v0, v1);
                        }
                    }
                }
            }
}

// ---------------------------------------------------------------------------
// tf32 flash attention, 128-thread CTAs (Bq=64, 4 warps x 16 q-rows),
// 2-stage K/V cp.async, 3 CTAs/SM. Q fragments via direct LDG (no Qs),
// P kept in registers and quad-shuffled into the PV A-fragment (no Ps).
// ---------------------------------------------------------------------------
#define FL_C2 0.1803368801111f   /* 0.125 * log2(e) */
#define FLASH_SMEM (2 * (2*64*68) * 4)   // K + V, 2 stages: 69632 B

__global__ void __launch_bounds__(128, 3) flash_mma_kernel() {
    extern __shared__ float fsm[];
    float* Ks = fsm;                    // [2][64][68]  (c-major: Ks[c][d])
    float* Vs = fsm + 2 * 64 * 68;      // [2][64][68]  (d-major: Vs[d][c])

    int qt = 31 - blockIdx.x;           // heavy tiles first
    int h = blockIdx.y, b = blockIdx.z;
    int bh = b * NH + h;
    int q0 = qt * 64;
    int nkt = qt + 33;

    int tid = threadIdx.x;
    int w = tid >> 5, l = tid & 31, lg = l >> 2, lt = l & 3;
    int r0w = w * 16;

    const float* kb0 = g_kf + (size_t)bh * TKV * DH;
    const float* vb0 = g_vf + (size_t)bh * DH * TKV;   // transposed [d][tk]

    unsigned uKs = su32(Ks), uVs = su32(Vs);

    auto loadKV = [&](int buf, int kt) {
        const float* kb = kb0 + (size_t)kt * 64 * DH;
        const float* vb = vb0 + (size_t)kt * 64;
        float* Kd = Ks + buf * 64 * 68;
        float* Vd = Vs + buf * 64 * 68;
#pragma unroll
        for (int i = 0; i < 8; i++) {
            int id = tid + i * 128;
            int row = id >> 4, c4 = (id & 15) << 2;
            cpa16(Kd + row * 68 + c4, kb + row * DH + c4);
            cpa16(Vd + row * 68 + c4, vb + (size_t)row * TKV + c4);
        }
    };

    loadKV(0, 0); CPC;
    loadKV(1, 1); CPC;

    // Q fragments straight from gmem (g_q already tf32-rounded).
    unsigned qF[8][4];
    {
        const float* q0p = g_q + ((size_t)bh * TQ + q0 + r0w + lg) * DH;
        const float* q8p = q0p + 8 * DH;
#pragma unroll
        for (int d8 = 0; d8 < 8; d8++) {
            int c = d8 * 8 + lt;
            qF[d8][0] = __float_as_uint(q0p[c]);
            qF[d8][1] = __float_as_uint(q8p[c]);
            qF[d8][2] = __float_as_uint(q0p[c + 4]);
            qF[d8][3] = __float_as_uint(q8p[c + 4]);
        }
    }

    float oacc[8][4];
    float mrow[2] = {-1e30f, -1e30f};
    float lrow[2] = {0.f, 0.f};
#pragma unroll
    for (int nt = 0; nt < 8; nt++)
#pragma unroll
        for (int c = 0; c < 4; c++) oacc[nt][c] = 0.f;

    int srcA = (l & 28) | (lt >> 1);   // 4*lg + lt/2
    int srcB = srcA + 2;
    bool odd = (lt & 1);

    int buf = 0;
    for (int kt = 0; kt < nkt; kt++) {
        CPW1; __syncthreads();
        unsigned kbase = uKs + (unsigned)(buf * 64 * 68) * 4u;
        unsigned vbase = uVs + (unsigned)(buf * 64 * 68) * 4u;

        // ---- S = Q @ K^T ----
        float sacc[8][4];
#pragma unroll
        for (int nt = 0; nt < 8; nt++)
#pragma unroll
            for (int c = 0; c < 4; c++) sacc[nt][c] = 0.f;

        unsigned bF[4];
#pragma unroll
        for (int d8 = 0; d8 < 8; d8++) {
#pragma unroll
            for (int ntp = 0; ntp < 4; ntp++) {
                int row = ntp * 16 + ((l >> 4) << 3) + (l & 7);
                int col = d8 * 8 + (((l >> 3) & 1) << 2);
                ldsm4(bF, kbase + (unsigned)(row * 68 + col) * 4u);
                mma8(sacc[2 * ntp], qF[d8], bF[0], bF[1]);
                mma8(sacc[2 * ntp + 1], qF[d8], bF[2], bF[3]);
            }
        }

        // ---- causal mask (only near the frontier) ----
        int thresh = q0 + 2048 - kt * 64;
        if (thresh < 64) {
            int rbase = r0w + lg;
#pragma unroll
            for (int nt = 0; nt < 8; nt++) {
                int jj0 = nt * 8 + 2 * lt;
#pragma unroll
                for (int cr = 0; cr < 4; cr++) {
                    int r = rbase + ((cr >> 1) << 3);
                    int jj = jj0 + (cr & 1);
                    if (jj > r + thresh) sacc[nt][cr] = -1e30f;
                }
            }
        }

        // ---- online softmax (warp-local, quad reduce) ----
#pragma unroll
        for (int g = 0; g < 2; g++) {
            float mx = -1e30f;
#pragma unroll
            for (int nt = 0; nt < 8; nt++)
                mx = fmaxf(mx, fmaxf(sacc[nt][2 * g], sacc[nt][2 * g + 1]));
            mx = fmaxf(mx, __shfl_xor_sync(0xffffffffu, mx, 1));
            mx = fmaxf(mx, __shfl_xor_sync(0xffffffffu, mx, 2));
            float mnew = fmaxf(mrow[g], mx);
            float alpha = ex2((mrow[g] - mnew) * FL_C2);
            mrow[g] = mnew;
            float sum = 0.f;
#pragma unroll
            for (int nt = 0; nt < 8; nt++) {
#pragma unroll
                for (int c = 0; c < 2; c++) {
                    float p = ex2((sacc[nt][2 * g + c] - mnew) * FL_C2);
                    sacc[nt][2 * g + c] = p;
                    sum += p;
                }
            }
            sum += __shfl_xor_sync(0xffffffffu, sum, 1);
            sum += __shfl_xor_sync(0xffffffffu, sum, 2);
            lrow[g] = lrow[g] * alpha + sum;
#pragma unroll
            for (int nt = 0; nt < 8; nt++) {
                oacc[nt][2 * g] *= alpha;
                oacc[nt][2 * g + 1] *= alpha;
            }
        }

        // ---- round P to tf32 ----
#pragma unroll
        for (int nt = 0; nt < 8; nt++)
#pragma unroll
            for (int c = 0; c < 4; c++) sacc[nt][c] = tfr(sacc[nt][c]);

        // ---- O += P @ V : P shuffled into A-fragments, V via LDSM ----
#pragma unroll
        for (int k8 = 0; k8 < 8; k8++) {
            float sA0 = __shfl_sync(0xffffffffu, sacc[k8][0], srcA);
            float sA1 = __shfl_sync(0xffffffffu, sacc[k8][1], srcA);
            float sA2 = __shfl_sync(0xffffffffu, sacc[k8][2], srcA);
            float sA3 = __shfl_sync(0xffffffffu, sacc[k8][3], srcA);
            float sB0 = __shfl_sync(0xffffffffu, sacc[k8][0], srcB);
            float sB1 = __shfl_sync(0xffffffffu, sacc[k8][1], srcB);
            float sB2 = __shfl_sync(0xffffffffu, sacc[k8][2], srcB);
            float sB3 = __shfl_sync(0xffffffffu, sacc[k8][3], srcB);
            unsigned aF[4];
            aF[0] = __float_as_uint(odd ? sA1 : sA0);
            aF[1] = __float_as_uint(odd ? sA3 : sA2);
            aF[2] = __float_as_uint(odd ? sB1 : sB0);
            aF[3] = __float_as_uint(odd ? sB3 : sB2);
#pragma unroll
            for (int ntp = 0; ntp < 4; ntp++) {
                int row = ntp * 16 + ((l >> 4) << 3) + (l & 7);
                int col = k8 * 8 + (((l >> 3) & 1) << 2);
                ldsm4(bF, vbase + (unsigned)(row * 68 + col) * 4u);
                mma8(oacc[2 * ntp], aF, bF[0], bF[1]);
                mma8(oacc[2 * ntp + 1], aF, bF[2], bF[3]);
            }
        }

        __syncthreads();
        if (kt + 2 < nkt) loadKV(buf, kt + 2);
        CPC;
        buf ^= 1;
    }

    // ---- epilogue: O/l -> g_attn[b, t, h*64+d] (tf32-rounded) ----
#pragma unroll
    for (int g = 0; g < 2; g++) {
        float inv = 1.f / lrow[g];
        int rg = q0 + r0w + lg + 8 * g;
        float* ob = g_attn + ((size_t)b * TQ + rg) * CM + h * DH;
#pragma unroll
        for (int nt = 0; nt < 8; nt++) {
            *(float2*)(ob + nt * 8 + 2 * lt) =
                make_float2(tfr(oacc[nt][2 * g] * inv),
                            tfr(oacc[nt][2 * g + 1] * inv));
        }
    }
}

// ---------------------------------------------------------------------------
extern "C" void kernel_launch(void* const* d_in, const int* in_sizes, int n_in,
                              void* d_out, int out_size) {
    const float* x  = (const float*)d_in[0];
    const float* kc = (const float*)d_in[1];
    const float* vc = (const float*)d_in[2];
    const float* Wq = (const float*)d_in[3];
    const float* bq = (const float*)d_in[4];
    const float* Wk = (const float*)d_in[5];
    const float* bk = (const float*)d_in[6];
    const float* Wv = (const float*)d_in[7];
    const float* bv = (const float*)d_in[8];
    const float* Wo = (const float*)d_in[9];
    const float* bo = (const float*)d_in[10];
    float* out = (float*)d_out;
    (void)in_sizes; (void)n_in;

    int tail = (out_size >= OUT_ELEMS + 2 * KV_ELEMS);

    cudaFuncSetAttribute(flash_mma_kernel,
                         cudaFuncAttributeMaxDynamicSharedMemorySize, FLASH_SMEM);
    cudaFuncSetAttribute(mma_gemm_kernel<1, 1>,
                         cudaFuncAttributeMaxDynamicSharedMemorySize, GEMM_SMEM);
    cudaFuncSetAttribute(mma_gemm_kernel<1, 0>,
                         cudaFuncAttributeMaxDynamicSharedMemorySize, GEMM_SMEM);
    cudaFuncSetAttribute(mma_gemm_kernel<0, 0>,
                         cudaFuncAttributeMaxDynamicSharedMemorySize, GEMM_SMEM);

    // Fused pre-pass: cache copy + tf32 rounding + V transpose, one launch
    if (tail)
        prepass_kernel<1><<<PREPASS_BLOCKS, 256>>>(
            (const float4*)x, (const float4*)kc, (const float4*)vc,
            (const float4*)Wq, (const float4*)Wk, (const float4*)Wv,
            (const float4*)Wo, vc,
            (float4*)(out + OUT_ELEMS), (float4*)(out + OUT_ELEMS + KV_ELEMS));
    else
        prepass_kernel<0><<<PREPASS_BLOCKS, 256>>>(
            (const float4*)x, (const float4*)kc, (const float4*)vc,
            (const float4*)Wq, (const float4*)Wk, (const float4*)Wv,
            (const float4*)Wo, vc, nullptr, nullptr);

    // Fused QKV projection: one launch, 768 CTAs
    dim3 qkvgrid(24, (BB * TQ) / 128);
    if (tail)
        mma_gemm_kernel<1, 1><<<qkvgrid, 256, GEMM_SMEM>>>(
            bq, bk, bv, out + OUT_ELEMS);
    else
        mma_gemm_kernel<1, 0><<<qkvgrid, 256, GEMM_SMEM>>>(
            bq, bk, bv, nullptr);

    flash_mma_kernel<<<dim3(TQ / 64, NH, BB), 128, FLASH_SMEM>>>();

    mma_gemm_kernel<0, 0><<<dim3(CM / 128, (BB * TQ) / 128), 256, GEMM_SMEM>>>(
        bo, nullptr, nullptr, out);
}

// round 14
// speedup vs baseline: 4.0180x; 1.0072x over previous
#include <cuda_runtime.h>
#include <math.h>
#include <float.h>

// Problem dims
#define BB   2
#define TQ   2048
#define CM   1024
#define NH   16
#define DH   64
#define TKV  4096
#define OUT_ELEMS (BB*TQ*CM)            // 4194304
#define KV_ELEMS  (BB*NH*TKV*DH)        // 8388608

// Scratch (device globals; allocation-free)
__device__ __align__(16) float g_q[BB*NH*TQ*DH];    // [b,h,t,d]  tf32-rounded
__device__ __align__(16) float g_kf[KV_ELEMS];      // [b,h,tk,d]
__device__ __align__(16) float g_vf[KV_ELEMS];      // [b,h,d,tk]  TRANSPOSED
__device__ __align__(16) float g_attn[OUT_ELEMS];   // [b,t,c]    tf32-rounded
__device__ __align__(16) float g_xr[OUT_ELEMS];     // x rounded to tf32
__device__ __align__(16) float g_wr[4*CM*CM];       // W^T (rounded): [ws][n][k]

// ---------------------------------------------------------------------------
// PTX helpers
// ---------------------------------------------------------------------------
__device__ __forceinline__ unsigned su32(const void* p) {
    return (unsigned)__cvta_generic_to_shared(p);
}
__device__ __forceinline__ void cpa16(void* d, const void* s) {
    asm volatile("cp.async.cg.shared.global [%0], [%1], 16;"
                 :: "r"(su32(d)), "l"(s));
}
#define CPC  asm volatile("cp.async.commit_group;")
#define CPW1 asm volatile("cp.async.wait_group 1;")
#define CPW2 asm volatile("cp.async.wait_group 2;")

__device__ __forceinline__ void ldsm4(unsigned* r, unsigned a) {
    asm volatile("ldmatrix.sync.aligned.m8n8.x4.shared.b16 {%0,%1,%2,%3}, [%4];"
                 : "=r"(r[0]), "=r"(r[1]), "=r"(r[2]), "=r"(r[3]) : "r"(a));
}
__device__ __forceinline__ void mma8(float* c, const unsigned* a,
                                     unsigned b0, unsigned b1) {
    asm volatile(
        "mma.sync.aligned.m16n8k8.row.col.f32.tf32.tf32.f32 "
        "{%0,%1,%2,%3}, {%4,%5,%6,%7}, {%8,%9}, {%0,%1,%2,%3};\n"
        : "+f"(c[0]), "+f"(c[1]), "+f"(c[2]), "+f"(c[3])
        : "r"(a[0]), "r"(a[1]), "r"(a[2]), "r"(a[3]), "r"(b0), "r"(b1));
}
__device__ __forceinline__ float tfr(float x) {   // round-to-nearest tf32
    unsigned u;
    asm("cvt.rna.tf32.f32 %0, %1;" : "=r"(u) : "f"(x));
    return __uint_as_float(u);
}
__device__ __forceinline__ float ex2(float x) {
    float y; asm("ex2.approx.f32 %0, %1;" : "=f"(y) : "f"(x)); return y;
}

// ---------------------------------------------------------------------------
// Fused pre-pass: one launch, block-range dispatch.
//   [0, 4096):      copy kv cache rows into g_kf (+ exact out tails)
//   [4096, 8192):   round x to tf32 -> g_xr
//   [8192, 12288):  transpose v cache [bh][t][d] -> g_vf [bh][d][t]
//   [12288, 16384): transpose+round W: g_wr[ws][n][k] = tfr(W[k][n])
// ---------------------------------------------------------------------------
#define PREPASS_BLOCKS 16384

template <int TAIL>
__global__ void __launch_bounds__(256) prepass_kernel(
    const float4* __restrict__ x,
    const float4* __restrict__ kc, const float4* __restrict__ vc,
    const float* __restrict__ wq, const float* __restrict__ wk,
    const float* __restrict__ wv, const float* __restrict__ wo,
    const float* __restrict__ vcf,
    float4* __restrict__ out_k, float4* __restrict__ out_v) {
    __shared__ float tile[32][33];
    int blk = blockIdx.x;
    if (blk < 4096) {
        // --- kv cache copy (1048576 float4) ---
        int idx = blk * 256 + threadIdx.x;
        int e  = idx << 2;
        int d  = e & (DH - 1);
        int t  = (e >> 6) & 2047;
        int bh = e >> 17;
        int dst4 = (((bh * TKV) + t) * DH + d) >> 2;
        float4 kv = kc[idx];
        ((float4*)g_kf)[dst4] = kv;
        if (TAIL) { out_k[dst4] = kv; out_v[dst4] = vc[idx]; }
    } else if (blk < 8192) {
        // --- x tf32 rounding (1048576 float4) ---
        int i = (blk - 4096) * 256 + threadIdx.x;
        float4 v = x[i];
        v.x = tfr(v.x); v.y = tfr(v.y); v.z = tfr(v.z); v.w = tfr(v.w);
        ((float4*)g_xr)[i] = v;
    } else if (blk < 12288) {
        // --- v cache transpose (4096 32x32 tiles) ---
        int tb = blk - 8192;
        int bh = tb >> 7;
        int rem = tb & 127;
        int c0 = (rem & 63) * 32, d0 = (rem >> 6) * 32;
        int tx = threadIdx.x & 31, ty = threadIdx.x >> 5;   // 32 x 8
        const float* src = vcf + ((size_t)bh * 2048 + c0) * DH + d0;
#pragma unroll
        for (int j = 0; j < 32; j += 8)
            tile[ty + j][tx] = src[(size_t)(ty + j) * DH + tx];
        __syncthreads();
        float* dst = g_vf + ((size_t)bh * DH + d0) * TKV + c0;
#pragma unroll
        for (int j = 0; j < 32; j += 8)
            dst[(size_t)(ty + j) * TKV + tx] = tile[tx][ty + j];
    } else {
        // --- W transpose + round (4 matrices x 1024 32x32 tiles) ---
        int tw = blk - 12288;
        int ws = tw >> 10;
        int rem = tw & 1023;
        int k0 = (rem & 31) * 32, n0 = (rem >> 5) * 32;
        const float* Wsrc = (ws == 0) ? wq : (ws == 1) ? wk
                          : (ws == 2) ? wv : wo;
        int tx = threadIdx.x & 31, ty = threadIdx.x >> 5;   // 32 x 8
#pragma unroll
        for (int j = 0; j < 32; j += 8)
            tile[ty + j][tx] = Wsrc[(size_t)(k0 + ty + j) * CM + n0 + tx];
        __syncthreads();
        float* dst = g_wr + (size_t)ws * CM * CM;
#pragma unroll
        for (int j = 0; j < 32; j += 8)
            dst[(size_t)(n0 + ty + j) * CM + k0 + tx] = tfr(tile[tx][ty + j]);
    }
}

// ---------------------------------------------------------------------------
// tf32 tensor-core GEMM: 128x128 tile, kc=16, 4-stage one-sync pipeline.
// BOTH operands via ldmatrix: A tile [128 m][16 k], B tile [128 n][16 k]
// (weights stored transposed in g_wr), each padded to stride 20.
// 8 warps: 4(m) x 2(n); warp tile 32m x 64n.
// ---------------------------------------------------------------------------
#define GEMM_SMEM ((4*128*20 + 4*128*20) * 4)   // 81920 B

template <int MODE, int TAIL>
__global__ void __launch_bounds__(256, 2)
mma_gemm_kernel(const float* __restrict__ b0p, const float* __restrict__ b1p,
                const float* __restrict__ b2p, float* __restrict__ Cout) {
    extern __shared__ float gsm[];
    float* As = gsm;                 // [4][128][20]  (m-major)
    float* Bs = gsm + 4 * 128 * 20;  // [4][128][20]  (n-major, from W^T)

    int sec, n0;
    const float* Ap; const float* WpT; const float* bias;
    if (MODE == 0) {
        Ap = g_attn; WpT = g_wr + (size_t)3 * CM * CM; bias = b0p;
        n0 = blockIdx.x * 128; sec = 0;
    } else {
        Ap = g_xr;
        sec = blockIdx.x >> 3;
        n0 = (blockIdx.x & 7) * 128;
        WpT = g_wr + (size_t)sec * CM * CM;
        bias = (sec == 0) ? b0p : (sec == 1) ? b1p : b2p;
    }

    int tid = threadIdx.x;
    int w = tid >> 5, l = tid & 31, lg = l >> 2, lt = l & 3;
    int wm = w & 3, wn = w >> 2;
    int m0 = blockIdx.y * 128;

    auto loadAB = [&](int buf, int kt) {
        int k0 = kt * 16;
        float* Ad = As + buf * 2560;
        float* Bd = Bs + buf * 2560;
#pragma unroll
        for (int i = 0; i < 2; i++) {
            int id = tid + i * 256;
            int row = id >> 2, c4 = (id & 3) << 2;
            cpa16(Ad + row * 20 + c4, Ap + (size_t)(m0 + row) * CM + k0 + c4);
            cpa16(Bd + row * 20 + c4, WpT + (size_t)(n0 + row) * CM + k0 + c4);
        }
    };

    float acc[2][8][4];
#pragma unroll
    for (int mt = 0; mt < 2; mt++)
#pragma unroll
        for (int nt = 0; nt < 8; nt++)
#pragma unroll
            for (int c = 0; c < 4; c++) acc[mt][nt][c] = 0.f;

    unsigned uAs = su32(As), uBs = su32(Bs);

    loadAB(0, 0); CPC;
    loadAB(1, 1); CPC;
    loadAB(2, 2); CPC;

    const int NKT = CM / 16;   // 64
    for (int kt = 0; kt < NKT; kt++) {
        CPW2; __syncthreads();
        if (kt + 3 < NKT) loadAB((kt + 3) & 3, kt + 3);
        CPC;   // empty commits near the tail keep wait_group arithmetic exact
        int buf = kt & 3;
        unsigned aBase = uAs + (unsigned)(buf * 2560) * 4u;
        unsigned bBase = uBs + (unsigned)(buf * 2560) * 4u;
#pragma unroll
        for (int ks = 0; ks < 2; ks++) {
            unsigned aF[2][4], bF[4];
#pragma unroll
            for (int mt = 0; mt < 2; mt++) {
                int row = wm * 32 + mt * 16 + (((l >> 3) & 1) << 3) + (l & 7);
                int col = ks * 8 + ((l >> 4) << 2);
                ldsm4(aF[mt], aBase + (unsigned)(row * 20 + col) * 4u);
            }
#pragma unroll
            for (int ntp = 0; ntp < 4; ntp++) {
                int row = wn * 64 + ntp * 16 + ((l >> 4) << 3) + (l & 7);
                int col = ks * 8 + (((l >> 3) & 1) << 2);
                ldsm4(bF, bBase + (unsigned)(row * 20 + col) * 4u);
                mma8(acc[0][2 * ntp],     aF[0], bF[0], bF[1]);
                mma8(acc[0][2 * ntp + 1], aF[0], bF[2], bF[3]);
                mma8(acc[1][2 * ntp],     aF[1], bF[0], bF[1]);
                mma8(acc[1][2 * ntp + 1], aF[1], bF[2], bF[3]);
            }
        }
    }

    // Epilogue
#pragma unroll
    for (int mt = 0; mt < 2; mt++)
#pragma unroll
        for (int nt = 0; nt < 8; nt++)
#pragma unroll
            for (int g = 0; g < 2; g++) {
                int m = m0 + wm * 32 + mt * 16 + lg + 8 * g;
                int n = n0 + wn * 64 + nt * 8 + 2 * lt;
                float v0 = acc[mt][nt][2 * g] + bias[n];
                float v1 = acc[mt][nt][2 * g + 1] + bias[n + 1];
                if (MODE == 0) {
                    *(float2*)&Cout[(size_t)m * CM + n] = make_float2(v0, v1);
                } else {
                    int b = m >> 11, t = m & 2047;
                    int h = n >> 6, d = n & 63;
                    int bh = b * NH + h;
                    if (sec == 0) {
                        size_t off = ((size_t)bh * TQ + t) * DH + d;
                        *(float2*)(g_q + off) = make_float2(tfr(v0), tfr(v1));
                    } else if (sec == 1) {
                        size_t off = ((size_t)bh * TKV + 2048 + t) * DH + d;
                        *(float2*)(g_kf + off) = make_float2(tfr(v0), tfr(v1));
                        if (TAIL)
                            *(float2*)(Cout + off) = make_float2(v0, v1);
                    } else {
                        size_t offT = ((size_t)bh * DH + d) * TKV + 2048 + t;
                        g_vf[offT]       = tfr(v0);
                        g_vf[offT + TKV] = tfr(v1);
                        if (TAIL) {
                            size_t off = ((size_t)bh * TKV + 2048 + t) * DH + d;
                            *(float2*)(Cout + KV_ELEMS + off) = make_float2(v0, v1);
                        }
                    }
                }
            }
}

// ---------------------------------------------------------------------------
// tf32 flash attention, 128-thread CTAs (Bq=64, 4 warps x 16 q-rows),
// 2-stage K/V cp.async, 3 CTAs/SM. Q fragments via direct LDG (no Qs),
// P kept in registers and quad-shuffled into the PV A-fragment (no Ps).
// ---------------------------------------------------------------------------
#define FL_C2 0.1803368801111f   /* 0.125 * log2(e) */
#define FLASH_SMEM (2 * (2*64*68) * 4)   // K + V, 2 stages: 69632 B

__global__ void __launch_bounds__(128, 3) flash_mma_kernel() {
    extern __shared__ float fsm[];
    float* Ks = fsm;                    // [2][64][68]  (c-major: Ks[c][d])
    float* Vs = fsm + 2 * 64 * 68;      // [2][64][68]  (d-major: Vs[d][c])

    int qt = 31 - blockIdx.x;           // heavy tiles first
    int h = blockIdx.y, b = blockIdx.z;
    int bh = b * NH + h;
    int q0 = qt * 64;
    int nkt = qt + 33;

    int tid = threadIdx.x;
    int w = tid >> 5, l = tid & 31, lg = l >> 2, lt = l & 3;
    int r0w = w * 16;

    const float* kb0 = g_kf + (size_t)bh * TKV * DH;
    const float* vb0 = g_vf + (size_t)bh * DH * TKV;   // transposed [d][tk]

    unsigned uKs = su32(Ks), uVs = su32(Vs);

    auto loadKV = [&](int buf, int kt) {
        const float* kb = kb0 + (size_t)kt * 64 * DH;
        const float* vb = vb0 + (size_t)kt * 64;
        float* Kd = Ks + buf * 64 * 68;
        float* Vd = Vs + buf * 64 * 68;
#pragma unroll
        for (int i = 0; i < 8; i++) {
            int id = tid + i * 128;
            int row = id >> 4, c4 = (id & 15) << 2;
            cpa16(Kd + row * 68 + c4, kb + row * DH + c4);
            cpa16(Vd + row * 68 + c4, vb + (size_t)row * TKV + c4);
        }
    };

    loadKV(0, 0); CPC;
    loadKV(1, 1); CPC;

    // Q fragments straight from gmem (g_q already tf32-rounded).
    unsigned qF[8][4];
    {
        const float* q0p = g_q + ((size_t)bh * TQ + q0 + r0w + lg) * DH;
        const float* q8p = q0p + 8 * DH;
#pragma unroll
        for (int d8 = 0; d8 < 8; d8++) {
            int c = d8 * 8 + lt;
            qF[d8][0] = __float_as_uint(q0p[c]);
            qF[d8][1] = __float_as_uint(q8p[c]);
            qF[d8][2] = __float_as_uint(q0p[c + 4]);
            qF[d8][3] = __float_as_uint(q8p[c + 4]);
        }
    }

    float oacc[8][4];
    float mrow[2] = {-1e30f, -1e30f};
    float lrow[2] = {0.f, 0.f};
#pragma unroll
    for (int nt = 0; nt < 8; nt++)
#pragma unroll
        for (int c = 0; c < 4; c++) oacc[nt][c] = 0.f;

    int srcA = (l & 28) | (lt >> 1);   // 4*lg + lt/2
    int srcB = srcA + 2;
    bool odd = (lt & 1);

    int buf = 0;
    for (int kt = 0; kt < nkt; kt++) {
        CPW1; __syncthreads();
        unsigned kbase = uKs + (unsigned)(buf * 64 * 68) * 4u;
        unsigned vbase = uVs + (unsigned)(buf * 64 * 68) * 4u;

        // ---- S = Q @ K^T ----
        float sacc[8][4];
#pragma unroll
        for (int nt = 0; nt < 8; nt++)
#pragma unroll
            for (int c = 0; c < 4; c++) sacc[nt][c] = 0.f;

        unsigned bF[4];
#pragma unroll
        for (int d8 = 0; d8 < 8; d8++) {
#pragma unroll
            for (int ntp = 0; ntp < 4; ntp++) {
                int row = ntp * 16 + ((l >> 4) << 3) + (l & 7);
                int col = d8 * 8 + (((l >> 3) & 1) << 2);
                ldsm4(bF, kbase + (unsigned)(row * 68 + col) * 4u);
                mma8(sacc[2 * ntp], qF[d8], bF[0], bF[1]);
                mma8(sacc[2 * ntp + 1], qF[d8], bF[2], bF[3]);
            }
        }

        // ---- causal mask (only near the frontier) ----
        int thresh = q0 + 2048 - kt * 64;
        if (thresh < 64) {
            int rbase = r0w + lg;
#pragma unroll
            for (int nt = 0; nt < 8; nt++) {
                int jj0 = nt * 8 + 2 * lt;
#pragma unroll
                for (int cr = 0; cr < 4; cr++) {
                    int r = rbase + ((cr >> 1) << 3);
                    int jj = jj0 + (cr & 1);
                    if (jj > r + thresh) sacc[nt][cr] = -1e30f;
                }
            }
        }

        // ---- online softmax (warp-local, quad reduce) ----
#pragma unroll
        for (int g = 0; g < 2; g++) {
            float mx = -1e30f;
#pragma unroll
            for (int nt = 0; nt < 8; nt++)
                mx = fmaxf(mx, fmaxf(sacc[nt][2 * g], sacc[nt][2 * g + 1]));
            mx = fmaxf(mx, __shfl_xor_sync(0xffffffffu, mx, 1));
            mx = fmaxf(mx, __shfl_xor_sync(0xffffffffu, mx, 2));
            float mnew = fmaxf(mrow[g], mx);
            float alpha = ex2((mrow[g] - mnew) * FL_C2);
            mrow[g] = mnew;
            float sum = 0.f;
#pragma unroll
            for (int nt = 0; nt < 8; nt++) {
#pragma unroll
                for (int c = 0; c < 2; c++) {
                    float p = ex2((sacc[nt][2 * g + c] - mnew) * FL_C2);
                    sacc[nt][2 * g + c] = p;
                    sum += p;
                }
            }
            sum += __shfl_xor_sync(0xffffffffu, sum, 1);
            sum += __shfl_xor_sync(0xffffffffu, sum, 2);
            lrow[g] = lrow[g] * alpha + sum;
#pragma unroll
            for (int nt = 0; nt < 8; nt++) {
                oacc[nt][2 * g] *= alpha;
                oacc[nt][2 * g + 1] *= alpha;
            }
        }

        // ---- round P to tf32 ----
#pragma unroll
        for (int nt = 0; nt < 8; nt++)
#pragma unroll
            for (int c = 0; c < 4; c++) sacc[nt][c] = tfr(sacc[nt][c]);

        // ---- O += P @ V : P shuffled into A-fragments, V via LDSM ----
#pragma unroll
        for (int k8 = 0; k8 < 8; k8++) {
            float sA0 = __shfl_sync(0xffffffffu, sacc[k8][0], srcA);
            float sA1 = __shfl_sync(0xffffffffu, sacc[k8][1], srcA);
            float sA2 = __shfl_sync(0xffffffffu, sacc[k8][2], srcA);
            float sA3 = __shfl_sync(0xffffffffu, sacc[k8][3], srcA);
            float sB0 = __shfl_sync(0xffffffffu, sacc[k8][0], srcB);
            float sB1 = __shfl_sync(0xffffffffu, sacc[k8][1], srcB);
            float sB2 = __shfl_sync(0xffffffffu, sacc[k8][2], srcB);
            float sB3 = __shfl_sync(0xffffffffu, sacc[k8][3], srcB);
            unsigned aF[4];
            aF[0] = __float_as_uint(odd ? sA1 : sA0);
            aF[1] = __float_as_uint(odd ? sA3 : sA2);
            aF[2] = __float_as_uint(odd ? sB1 : sB0);
            aF[3] = __float_as_uint(odd ? sB3 : sB2);
#pragma unroll
            for (int ntp = 0; ntp < 4; ntp++) {
                int row = ntp * 16 + ((l >> 4) << 3) + (l & 7);
                int col = k8 * 8 + (((l >> 3) & 1) << 2);
                ldsm4(bF, vbase + (unsigned)(row * 68 + col) * 4u);
                mma8(oacc[2 * ntp], aF, bF[0], bF[1]);
                mma8(oacc[2 * ntp + 1], aF, bF[2], bF[3]);
            }
        }

        __syncthreads();
        if (kt + 2 < nkt) loadKV(buf, kt + 2);
        CPC;
        buf ^= 1;
    }

    // ---- epilogue: O/l -> g_attn[b, t, h*64+d] (tf32-rounded) ----
#pragma unroll
    for (int g = 0; g < 2; g++) {
        float inv = 1.f / lrow[g];
        int rg = q0 + r0w + lg + 8 * g;
        float* ob = g_attn + ((size_t)b * TQ + rg) * CM + h * DH;
#pragma unroll
        for (int nt = 0; nt < 8; nt++) {
            *(float2*)(ob + nt * 8 + 2 * lt) =
                make_float2(tfr(oacc[nt][2 * g] * inv),
                            tfr(oacc[nt][2 * g + 1] * inv));
        }
    }
}

// ---------------------------------------------------------------------------
extern "C" void kernel_launch(void* const* d_in, const int* in_sizes, int n_in,
                              void* d_out, int out_size) {
    const float* x  = (const float*)d_in[0];
    const float* kc = (const float*)d_in[1];
    const float* vc = (const float*)d_in[2];
    const float* Wq = (const float*)d_in[3];
    const float* bq = (const float*)d_in[4];
    const float* Wk = (const float*)d_in[5];
    const float* bk = (const float*)d_in[6];
    const float* Wv = (const float*)d_in[7];
    const float* bv = (const float*)d_in[8];
    const float* Wo = (const float*)d_in[9];
    const float* bo = (const float*)d_in[10];
    float* out = (float*)d_out;
    (void)in_sizes; (void)n_in;

    int tail = (out_size >= OUT_ELEMS + 2 * KV_ELEMS);

    cudaFuncSetAttribute(flash_mma_kernel,
                         cudaFuncAttributeMaxDynamicSharedMemorySize, FLASH_SMEM);
    cudaFuncSetAttribute(mma_gemm_kernel<1, 1>,
                         cudaFuncAttributeMaxDynamicSharedMemorySize, GEMM_SMEM);
    cudaFuncSetAttribute(mma_gemm_kernel<1, 0>,
                         cudaFuncAttributeMaxDynamicSharedMemorySize, GEMM_SMEM);
    cudaFuncSetAttribute(mma_gemm_kernel<0, 0>,
                         cudaFuncAttributeMaxDynamicSharedMemorySize, GEMM_SMEM);

    // Fused pre-pass: cache copy + x round + V transpose + W transpose/round
    if (tail)
        prepass_kernel<1><<<PREPASS_BLOCKS, 256>>>(
            (const float4*)x, (const float4*)kc, (const float4*)vc,
            Wq, Wk, Wv, Wo, vc,
            (float4*)(out + OUT_ELEMS), (float4*)(out + OUT_ELEMS + KV_ELEMS));
    else
        prepass_kernel<0><<<PREPASS_BLOCKS, 256>>>(
            (const float4*)x, (const float4*)kc, (const float4*)vc,
            Wq, Wk, Wv, Wo, vc, nullptr, nullptr);

    // Fused QKV projection: one launch, 768 CTAs
    dim3 qkvgrid(24, (BB * TQ) / 128);
    if (tail)
        mma_gemm_kernel<1, 1><<<qkvgrid, 256, GEMM_SMEM>>>(
            bq, bk, bv, out + OUT_ELEMS);
    else
        mma_gemm_kernel<1, 0><<<qkvgrid, 256, GEMM_SMEM>>>(
            bq, bk, bv, nullptr);

    flash_mma_kernel<<<dim3(TQ / 64, NH, BB), 128, FLASH_SMEM>>>();

    mma_gemm_kernel<0, 0><<<dim3(CM / 128, (BB * TQ) / 128), 256, GEMM_SMEM>>>(
        bo, nullptr, nullptr, out);
}

// round 17
// speedup vs baseline: 6.9746x; 1.7358x over previous
#include <cuda_runtime.h>
#include <cuda_fp16.h>
#include <cstdint>
#include <stdint.h>
#include <math.h>
#include <float.h>

// Problem dims
#define BB   2
#define TQ   2048
#define CM   1024
#define NH   16
#define DH   64
#define TKV  4096
#define OUT_ELEMS (BB*TQ*CM)            // 4194304
#define KV_ELEMS  (BB*NH*TKV*DH)        // 8388608

// Scratch (device globals; allocation-free) — fp16 operands, fp32 exact tails
__device__ __align__(16) __half g_qh[BB*NH*TQ*DH];  // [b,h,t,d]
__device__ __align__(16) __half g_kh[KV_ELEMS];     // [b,h,tk,d]
__device__ __align__(16) __half g_vt[KV_ELEMS];     // [b,h,d,tk] TRANSPOSED
__device__ __align__(16) __half g_ah[OUT_ELEMS];    // attn out [b,t,c]
__device__ __align__(16) __half g_xh[OUT_ELEMS];    // x in half
__device__ __align__(16) __half g_wh[4*CM*CM];      // W^T in half: [ws][n][k]

// ---------------------------------------------------------------------------
// PTX helpers
// ---------------------------------------------------------------------------
__device__ __forceinline__ unsigned su32(const void* p) {
    return (unsigned)__cvta_generic_to_shared(p);
}
__device__ __forceinline__ void cpa16(void* d, const void* s) {
    asm volatile("cp.async.cg.shared.global [%0], [%1], 16;"
                 :: "r"(su32(d)), "l"(s));
}
#define CPC  asm volatile("cp.async.commit_group;")
#define CPW1 asm volatile("cp.async.wait_group 1;")
#define CPW2 asm volatile("cp.async.wait_group 2;")

__device__ __forceinline__ void ldsm4(unsigned* r, unsigned a) {
    asm volatile("ldmatrix.sync.aligned.m8n8.x4.shared.b16 {%0,%1,%2,%3}, [%4];"
                 : "=r"(r[0]), "=r"(r[1]), "=r"(r[2]), "=r"(r[3]) : "r"(a));
}
// fp16 mma: D(f32) += A(f16,4regs) * B(f16,2regs)
__device__ __forceinline__ void mma16(float* c, const unsigned* a,
                                      unsigned b0, unsigned b1) {
    asm volatile(
        "mma.sync.aligned.m16n8k16.row.col.f32.f16.f16.f32 "
        "{%0,%1,%2,%3}, {%4,%5,%6,%7}, {%8,%9}, {%0,%1,%2,%3};\n"
        : "+f"(c[0]), "+f"(c[1]), "+f"(c[2]), "+f"(c[3])
        : "r"(a[0]), "r"(a[1]), "r"(a[2]), "r"(a[3]), "r"(b0), "r"(b1));
}
// pack two floats -> half2 register {lo, hi}
__device__ __forceinline__ unsigned packh2(float lo, float hi) {
    unsigned d;
    asm("cvt.rn.f16x2.f32 %0, %1, %2;" : "=r"(d) : "f"(hi), "f"(lo));
    return d;
}
__device__ __forceinline__ float ex2(float x) {
    float y; asm("ex2.approx.f32 %0, %1;" : "=f"(y) : "f"(x)); return y;
}

// ---------------------------------------------------------------------------
// Fused pre-pass: one launch, block-range dispatch.
//   [0, 4096):      kv cache -> g_kh (half) + exact fp32 out tails
//   [4096, 8192):   x -> g_xh (half)
//   [8192, 12288):  v cache transpose -> g_vt [bh][d][t] (half)
//   [12288, 16384): W transpose -> g_wh [ws][n][k] (half)
// ---------------------------------------------------------------------------
#define PREPASS_BLOCKS 16384

template <int TAIL>
__global__ void __launch_bounds__(256) prepass_kernel(
    const float4* __restrict__ x,
    const float4* __restrict__ kc, const float4* __restrict__ vc,
    const float* __restrict__ wq, const float* __restrict__ wk,
    const float* __restrict__ wv, const float* __restrict__ wo,
    const float* __restrict__ vcf,
    float4* __restrict__ out_k, float4* __restrict__ out_v) {
    __shared__ float tile[32][33];
    int blk = blockIdx.x;
    if (blk < 4096) {
        int idx = blk * 256 + threadIdx.x;
        int e  = idx << 2;
        int d  = e & (DH - 1);
        int t  = (e >> 6) & 2047;
        int bh = e >> 17;
        int dst4 = (((bh * TKV) + t) * DH + d) >> 2;
        float4 kv = kc[idx];
        uint2 kh;
        kh.x = packh2(kv.x, kv.y);
        kh.y = packh2(kv.z, kv.w);
        *(uint2*)(g_kh + (size_t)dst4 * 4) = kh;
        if (TAIL) { out_k[dst4] = kv; out_v[dst4] = vc[idx]; }
    } else if (blk < 8192) {
        int i = (blk - 4096) * 256 + threadIdx.x;
        float4 v = x[i];
        uint2 xh;
        xh.x = packh2(v.x, v.y);
        xh.y = packh2(v.z, v.w);
        *(uint2*)(g_xh + (size_t)i * 4) = xh;
    } else if (blk < 12288) {
        int tb = blk - 8192;
        int bh = tb >> 7;
        int rem = tb & 127;
        int c0 = (rem & 63) * 32, d0 = (rem >> 6) * 32;
        int tx = threadIdx.x & 31, ty = threadIdx.x >> 5;
        const float* src = vcf + ((size_t)bh * 2048 + c0) * DH + d0;
#pragma unroll
        for (int j = 0; j < 32; j += 8)
            tile[ty + j][tx] = src[(size_t)(ty + j) * DH + tx];
        __syncthreads();
        __half* dst = g_vt + ((size_t)bh * DH + d0) * TKV + c0;
#pragma unroll
        for (int j = 0; j < 32; j += 8)
            dst[(size_t)(ty + j) * TKV + tx] = __float2half_rn(tile[tx][ty + j]);
    } else {
        int tw = blk - 12288;
        int ws = tw >> 10;
        int rem = tw & 1023;
        int k0 = (rem & 31) * 32, n0 = (rem >> 5) * 32;
        const float* Wsrc = (ws == 0) ? wq : (ws == 1) ? wk
                          : (ws == 2) ? wv : wo;
        int tx = threadIdx.x & 31, ty = threadIdx.x >> 5;
#pragma unroll
        for (int j = 0; j < 32; j += 8)
            tile[ty + j][tx] = Wsrc[(size_t)(k0 + ty + j) * CM + n0 + tx];
        __syncthreads();
        __half* dst = g_wh + (size_t)ws * CM * CM;
#pragma unroll
        for (int j = 0; j < 32; j += 8)
            dst[(size_t)(n0 + ty + j) * CM + k0 + tx] =
                __float2half_rn(tile[tx][ty + j]);
    }
}

// ---------------------------------------------------------------------------
// fp16 tensor-core GEMM: 128x128 tile, kc=32/stage, 4-stage one-sync pipeline.
// A tile [128 m][32 k] half (stride 40), B tile [128 n][32 k] half (stride 40,
// from W^T). Both operands native ldmatrix fp16. 8 warps: 4(m) x 2(n).
// MODE 0: A=g_ah, W=Wo^T -> Cout fp32. MODE 1: fused QKV (sec = bx>>3).
// ---------------------------------------------------------------------------
#define GEMM_SMEM ((4*128*40 + 4*128*40) * 2)   // 81920 B

template <int MODE, int TAIL>
__global__ void __launch_bounds__(256, 2)
mma_gemm_kernel(const float* __restrict__ b0p, const float* __restrict__ b1p,
                const float* __restrict__ b2p, float* __restrict__ Cout) {
    extern __shared__ __half gsm[];
    __half* As = gsm;                  // [4][128][40]
    __half* Bs = gsm + 4 * 128 * 40;   // [4][128][40]

    int sec, n0;
    const __half* Ap; const __half* WpT; const float* bias;
    if (MODE == 0) {
        Ap = g_ah; WpT = g_wh + (size_t)3 * CM * CM; bias = b0p;
        n0 = blockIdx.x * 128; sec = 0;
    } else {
        Ap = g_xh;
        sec = blockIdx.x >> 3;
        n0 = (blockIdx.x & 7) * 128;
        WpT = g_wh + (size_t)sec * CM * CM;
        bias = (sec == 0) ? b0p : (sec == 1) ? b1p : b2p;
    }

    int tid = threadIdx.x;
    int w = tid >> 5, l = tid & 31, lg = l >> 2, lt = l & 3;
    int wm = w & 3, wn = w >> 2;
    int m0 = blockIdx.y * 128;

    auto loadAB = [&](int buf, int kt) {
        int k0 = kt * 32;
        __half* Ad = As + buf * 5120;
        __half* Bd = Bs + buf * 5120;
#pragma unroll
        for (int i = 0; i < 2; i++) {
            int id = tid + i * 256;            // 0..511
            int row = id >> 2, ch = (id & 3) << 3;   // 128 rows x 4 8-half chunks
            cpa16(Ad + row * 40 + ch, Ap + (size_t)(m0 + row) * CM + k0 + ch);
            cpa16(Bd + row * 40 + ch, WpT + (size_t)(n0 + row) * CM + k0 + ch);
        }
    };

    float acc[2][8][4];
#pragma unroll
    for (int mt = 0; mt < 2; mt++)
#pragma unroll
        for (int nt = 0; nt < 8; nt++)
#pragma unroll
            for (int c = 0; c < 4; c++) acc[mt][nt][c] = 0.f;

    unsigned uAs = su32(As), uBs = su32(Bs);

    loadAB(0, 0); CPC;
    loadAB(1, 1); CPC;
    loadAB(2, 2); CPC;

    const int NKT = CM / 32;   // 32
    for (int kt = 0; kt < NKT; kt++) {
        CPW2; __syncthreads();
        if (kt + 3 < NKT) loadAB((kt + 3) & 3, kt + 3);
        CPC;   // empty commits near the tail keep wait_group arithmetic exact
        int buf = kt & 3;
        unsigned aBase = uAs + (unsigned)(buf * 5120) * 2u;
        unsigned bBase = uBs + (unsigned)(buf * 5120) * 2u;
#pragma unroll
        for (int ks = 0; ks < 2; ks++) {
            unsigned aF[2][4], bF[4];
#pragma unroll
            for (int mt = 0; mt < 2; mt++) {
                int row = wm * 32 + mt * 16 + (l & 15);
                ldsm4(aF[mt], aBase +
                      (unsigned)((row * 40 + ks * 16) * 2 + (l >> 4) * 16));
            }
#pragma unroll
            for (int nt16 = 0; nt16 < 4; nt16++) {
                int row = wn * 64 + nt16 * 16 + (l & 15);
                ldsm4(bF, bBase +
                      (unsigned)((row * 40 + ks * 16) * 2 + (l >> 4) * 16));
                mma16(acc[0][2 * nt16],     aF[0], bF[0], bF[2]);
                mma16(acc[0][2 * nt16 + 1], aF[0], bF[1], bF[3]);
                mma16(acc[1][2 * nt16],     aF[1], bF[0], bF[2]);
                mma16(acc[1][2 * nt16 + 1], aF[1], bF[1], bF[3]);
            }
        }
    }

    // Epilogue (fp32 accum + bias; scatter)
#pragma unroll
    for (int mt = 0; mt < 2; mt++)
#pragma unroll
        for (int nt = 0; nt < 8; nt++)
#pragma unroll
            for (int g = 0; g < 2; g++) {
                int m = m0 + wm * 32 + mt * 16 + lg + 8 * g;
                int n = n0 + wn * 64 + nt * 8 + 2 * lt;
                float v0 = acc[mt][nt][2 * g] + bias[n];
                float v1 = acc[mt][nt][2 * g + 1] + bias[n + 1];
                if (MODE == 0) {
                    *(float2*)&Cout[(size_t)m * CM + n] = make_float2(v0, v1);
                } else {
                    int b = m >> 11, t = m & 2047;
                    int h = n >> 6, d = n & 63;
                    int bh = b * NH + h;
                    if (sec == 0) {
                        size_t off = ((size_t)bh * TQ + t) * DH + d;
                        *(unsigned*)(g_qh + off) = packh2(v0, v1);
                    } else if (sec == 1) {
                        size_t off = ((size_t)bh * TKV + 2048 + t) * DH + d;
                        *(unsigned*)(g_kh + off) = packh2(v0, v1);
                        if (TAIL)
                            *(float2*)(Cout + off) = make_float2(v0, v1);
                    } else {
                        size_t offT = ((size_t)bh * DH + d) * TKV + 2048 + t;
                        g_vt[offT]       = __float2half_rn(v0);
                        g_vt[offT + TKV] = __float2half_rn(v1);
                        if (TAIL) {
                            size_t off = ((size_t)bh * TKV + 2048 + t) * DH + d;
                            *(float2*)(Cout + KV_ELEMS + off) = make_float2(v0, v1);
                        }
                    }
                }
            }
}

// ---------------------------------------------------------------------------
// fp16 flash attention, 128-thread CTAs (Bq=64, 4 warps x 16 q-rows),
// 2-stage K/V cp.async, 4 CTAs/SM. Q fragments via direct LDG; P packed
// in-register to half2 A-fragments (no smem, no shuffles); K/V via native
// fp16 ldmatrix. fp32 accumulators + softmax throughout.
// ---------------------------------------------------------------------------
#define FL_C2 0.1803368801111f   /* 0.125 * log2(e) */
#define FLASH_SMEM (2 * (2*64*72) * 2)   // 36864 B

__global__ void __launch_bounds__(128, 4) flash_mma_kernel() {
    extern __shared__ __half fsh[];
    __half* Ks = fsh;                   // [2][64][72]  c-major: Ks[c][d]
    __half* Vs = fsh + 2 * 64 * 72;     // [2][64][72]  d-major: Vs[d][c]

    int qt = 31 - blockIdx.x;           // heavy tiles first
    int h = blockIdx.y, b = blockIdx.z;
    int bh = b * NH + h;
    int q0 = qt * 64;
    int nkt = qt + 33;

    int tid = threadIdx.x;
    int w = tid >> 5, l = tid & 31, lg = l >> 2, lt = l & 3;
    int r0w = w * 16;

    const __half* kb0 = g_kh + (size_t)bh * TKV * DH;
    const __half* vb0 = g_vt + (size_t)bh * DH * TKV;

    unsigned uKs = su32(Ks), uVs = su32(Vs);

    auto loadKV = [&](int buf, int kt) {
        const __half* kb = kb0 + (size_t)kt * 64 * DH;
        const __half* vb = vb0 + (size_t)kt * 64;
        __half* Kd = Ks + buf * 64 * 72;
        __half* Vd = Vs + buf * 64 * 72;
#pragma unroll
        for (int i = 0; i < 4; i++) {
            int id = tid + i * 128;            // 0..511
            int row = id >> 3, ch = (id & 7) << 3;
            cpa16(Kd + row * 72 + ch, kb + row * DH + ch);
            cpa16(Vd + row * 72 + ch, vb + (size_t)row * TKV + ch);
        }
    };

    loadKV(0, 0); CPC;
    loadKV(1, 1); CPC;

    // Q fragments straight from gmem (half2 pairs; even offsets -> 4B aligned)
    unsigned qF[4][4];
    {
        const __half* q0p = g_qh + ((size_t)bh * TQ + q0 + r0w + lg) * DH;
        const __half* q8p = q0p + 8 * DH;
#pragma unroll
        for (int dt = 0; dt < 4; dt++) {
            int c = dt * 16 + 2 * lt;
            qF[dt][0] = *(const unsigned*)(q0p + c);
            qF[dt][1] = *(const unsigned*)(q8p + c);
            qF[dt][2] = *(const unsigned*)(q0p + c + 8);
            qF[dt][3] = *(const unsigned*)(q8p + c + 8);
        }
    }

    float oacc[8][4];
    float mrow[2] = {-1e30f, -1e30f};
    float lrow[2] = {0.f, 0.f};
#pragma unroll
    for (int nt = 0; nt < 8; nt++)
#pragma unroll
        for (int c = 0; c < 4; c++) oacc[nt][c] = 0.f;

    int buf = 0;
    for (int kt = 0; kt < nkt; kt++) {
        CPW1; __syncthreads();
        unsigned kbase = uKs + (unsigned)(buf * 64 * 72) * 2u;
        unsigned vbase = uVs + (unsigned)(buf * 64 * 72) * 2u;

        // ---- S = Q @ K^T  (A=Q frags, B=K c-major native ldsm) ----
        float sacc[8][4];
#pragma unroll
        for (int nt = 0; nt < 8; nt++)
#pragma unroll
            for (int c = 0; c < 4; c++) sacc[nt][c] = 0.f;

        unsigned bF[4];
#pragma unroll
        for (int dt = 0; dt < 4; dt++) {
#pragma unroll
            for (int ct = 0; ct < 4; ct++) {
                int row = ct * 16 + (l & 15);
                ldsm4(bF, kbase +
                      (unsigned)((row * 72 + dt * 16) * 2 + (l >> 4) * 16));
                mma16(sacc[2 * ct],     qF[dt], bF[0], bF[2]);
                mma16(sacc[2 * ct + 1], qF[dt], bF[1], bF[3]);
            }
        }

        // ---- causal mask (only near the frontier) ----
        int thresh = q0 + 2048 - kt * 64;
        if (thresh < 64) {
            int rbase = r0w + lg;
#pragma unroll
            for (int nt = 0; nt < 8; nt++) {
                int jj0 = nt * 8 + 2 * lt;
#pragma unroll
                for (int cr = 0; cr < 4; cr++) {
                    int r = rbase + ((cr >> 1) << 3);
                    int jj = jj0 + (cr & 1);
                    if (jj > r + thresh) sacc[nt][cr] = -1e30f;
                }
            }
        }

        // ---- online softmax (warp-local, quad reduce) ----
#pragma unroll
        for (int g = 0; g < 2; g++) {
            float mx = -1e30f;
#pragma unroll
            for (int nt = 0; nt < 8; nt++)
                mx = fmaxf(mx, fmaxf(sacc[nt][2 * g], sacc[nt][2 * g + 1]));
            mx = fmaxf(mx, __shfl_xor_sync(0xffffffffu, mx, 1));
            mx = fmaxf(mx, __shfl_xor_sync(0xffffffffu, mx, 2));
            float mnew = fmaxf(mrow[g], mx);
            float alpha = ex2((mrow[g] - mnew) * FL_C2);
            mrow[g] = mnew;
            float sum = 0.f;
#pragma unroll
            for (int nt = 0; nt < 8; nt++) {
#pragma unroll
                for (int c = 0; c < 2; c++) {
                    float p = ex2((sacc[nt][2 * g + c] - mnew) * FL_C2);
                    sacc[nt][2 * g + c] = p;
                    sum += p;
                }
            }
            sum += __shfl_xor_sync(0xffffffffu, sum, 1);
            sum += __shfl_xor_sync(0xffffffffu, sum, 2);
            lrow[g] = lrow[g] * alpha + sum;
#pragma unroll
            for (int nt = 0; nt < 8; nt++) {
                oacc[nt][2 * g] *= alpha;
                oacc[nt][2 * g + 1] *= alpha;
            }
        }

        // ---- O += P @ V : P packed in-register to fp16 A-frags ----
#pragma unroll
        for (int kt2 = 0; kt2 < 4; kt2++) {
            unsigned aP[4];
            aP[0] = packh2(sacc[2 * kt2][0],     sacc[2 * kt2][1]);
            aP[1] = packh2(sacc[2 * kt2][2],     sacc[2 * kt2][3]);
            aP[2] = packh2(sacc[2 * kt2 + 1][0], sacc[2 * kt2 + 1][1]);
            aP[3] = packh2(sacc[2 * kt2 + 1][2], sacc[2 * kt2 + 1][3]);
#pragma unroll
            for (int dt4 = 0; dt4 < 4; dt4++) {
                int row = dt4 * 16 + (l & 15);
                ldsm4(bF, vbase +
                      (unsigned)((row * 72 + kt2 * 16) * 2 + (l >> 4) * 16));
                mma16(oacc[2 * dt4],     aP, bF[0], bF[2]);
                mma16(oacc[2 * dt4 + 1], aP, bF[1], bF[3]);
            }
        }

        __syncthreads();
        if (kt + 2 < nkt) loadKV(buf, kt + 2);
        CPC;
        buf ^= 1;
    }

    // ---- epilogue: O/l -> g_ah[b, t, h*64+d] (half) ----
#pragma unroll
    for (int g = 0; g < 2; g++) {
        float inv = 1.f / lrow[g];
        int rg = q0 + r0w + lg + 8 * g;
        __half* ob = g_ah + ((size_t)b * TQ + rg) * CM + h * DH;
#pragma unroll
        for (int nt = 0; nt < 8; nt++) {
            *(unsigned*)(ob + nt * 8 + 2 * lt) =
                packh2(oacc[nt][2 * g] * inv, oacc[nt][2 * g + 1] * inv);
        }
    }
}

// ---------------------------------------------------------------------------
extern "C" void kernel_launch(void* const* d_in, const int* in_sizes, int n_in,
                              void* d_out, int out_size) {
    const float* x  = (const float*)d_in[0];
    const float* kc = (const float*)d_in[1];
    const float* vc = (const float*)d_in[2];
    const float* Wq = (const float*)d_in[3];
    const float* bq = (const float*)d_in[4];
    const float* Wk = (const float*)d_in[5];
    const float* bk = (const float*)d_in[6];
    const float* Wv = (const float*)d_in[7];
    const float* bv = (const float*)d_in[8];
    const float* Wo = (const float*)d_in[9];
    const float* bo = (const float*)d_in[10];
    float* out = (float*)d_out;
    (void)in_sizes; (void)n_in;

    int tail = (out_size >= OUT_ELEMS + 2 * KV_ELEMS);

    cudaFuncSetAttribute(flash_mma_kernel,
                         cudaFuncAttributeMaxDynamicSharedMemorySize, FLASH_SMEM);
    cudaFuncSetAttribute(mma_gemm_kernel<1, 1>,
                         cudaFuncAttributeMaxDynamicSharedMemorySize, GEMM_SMEM);
    cudaFuncSetAttribute(mma_gemm_kernel<1, 0>,
                         cudaFuncAttributeMaxDynamicSharedMemorySize, GEMM_SMEM);
    cudaFuncSetAttribute(mma_gemm_kernel<0, 0>,
                         cudaFuncAttributeMaxDynamicSharedMemorySize, GEMM_SMEM);

    // Fused pre-pass: cache->half + x->half + V transpose + W transpose
    if (tail)
        prepass_kernel<1><<<PREPASS_BLOCKS, 256>>>(
            (const float4*)x, (const float4*)kc, (const float4*)vc,
            Wq, Wk, Wv, Wo, vc,
            (float4*)(out + OUT_ELEMS), (float4*)(out + OUT_ELEMS + KV_ELEMS));
    else
        prepass_kernel<0><<<PREPASS_BLOCKS, 256>>>(
            (const float4*)x, (const float4*)kc, (const float4*)vc,
            Wq, Wk, Wv, Wo, vc, nullptr, nullptr);

    // Fused QKV projection: one launch, 768 CTAs
    dim3 qkvgrid(24, (BB * TQ) / 128);
    if (tail)
        mma_gemm_kernel<1, 1><<<qkvgrid, 256, GEMM_SMEM>>>(
            bq, bk, bv, out + OUT_ELEMS);
    else
        mma_gemm_kernel<1, 0><<<qkvgrid, 256, GEMM_SMEM>>>(
            bq, bk, bv, nullptr);

    flash_mma_kernel<<<dim3(TQ / 64, NH, BB), 128, FLASH_SMEM>>>();

    mma_gemm_kernel<0, 0><<<dim3(CM / 128, (BB * TQ) / 128), 256, GEMM_SMEM>>>(
        bo, nullptr, nullptr, out);
}